// round 13
// baseline (speedup 1.0000x reference)
#include <cuda_runtime.h>
#include <cuda_bf16.h>
#include <math.h>
#include <stdint.h>

#define B_   64
#define T_   256
#define E_   512
#define H_   1024
#define G4H  4096
#define VT   64
#define NCTA 128
#define NTHR 512

__device__ float g_zx_enc[(long)T_ * B_ * G4H];
__device__ float g_dec_xw[VT * G4H];
__device__ __align__(16) __nv_bfloat16 g_hbf[2][B_][H_];   // [phase][b][k] bf16
__device__ float g_hs[(long)T_ * B_ * H_];
__device__ unsigned g_grp[4 * 32];   // 4 producer-group counters, one per 128B line

// ---- persistent-LSTM SMEM layout (bytes) ----
#define WPITCH 2064            // 1032 bf16 per W row (1024 + 8 pad)
#define SM_W   0               // single plane, 32 n-rows = 66048
#define APITCH 528             // 264 bf16 per A row (256 + 8 pad)
#define SM_A0  66048
#define SM_A1  99840
#define SM_Z   66048           // z planes ALIAS A0 (A0 dead when z written)
#define ZPLANE 8704            // [64][34] f32
#define SM_SDEC 133632         // [64 tok][32] f32 = 8192
#define SM_STOK 141824         // [64] int = 256
#define SM_TOT  142080

__device__ __forceinline__ void cpasync16(uint32_t dst, const void* src) {
    asm volatile("cp.async.cg.shared.global [%0], [%1], 16;" :: "r"(dst), "l"(src));
}
__device__ __forceinline__ void ldsm4(uint32_t* f, uint32_t addr) {
    asm volatile("ldmatrix.sync.aligned.m8n8.x4.shared.b16 {%0,%1,%2,%3}, [%4];"
        : "=r"(f[0]), "=r"(f[1]), "=r"(f[2]), "=r"(f[3]) : "r"(addr));
}
__device__ __forceinline__ void mma16816(float* c, const uint32_t* a,
                                         uint32_t b0, uint32_t b1) {
    asm volatile("mma.sync.aligned.m16n8k16.row.col.f32.bf16.bf16.f32 "
        "{%0,%1,%2,%3}, {%4,%5,%6,%7}, {%8,%9}, {%0,%1,%2,%3};"
        : "+f"(c[0]), "+f"(c[1]), "+f"(c[2]), "+f"(c[3])
        : "r"(a[0]), "r"(a[1]), "r"(a[2]), "r"(a[3]), "r"(b0), "r"(b1));
}
__device__ __forceinline__ float sigf(float x) {
    return __fdividef(1.f, 1.f + __expf(-x));
}
__device__ __forceinline__ unsigned long long pack2(float x) {
    unsigned long long r; asm("mov.b64 %0, {%1,%1};" : "=l"(r) : "f"(x)); return r;
}
__device__ __forceinline__ unsigned long long packab(float a, float b) {
    unsigned long long r; asm("mov.b64 %0, {%1,%2};" : "=l"(r) : "f"(a), "f"(b)); return r;
}
__device__ __forceinline__ void fma2(unsigned long long& d, unsigned long long a,
                                     unsigned long long b) {
    asm("fma.rn.f32x2 %0, %1, %2, %0;" : "+l"(d) : "l"(a), "l"(b));
}
__device__ __forceinline__ float2 unpack2(unsigned long long v) {
    float2 f; asm("mov.b64 {%0,%1}, %2;" : "=f"(f.x), "=f"(f.y) : "l"(v)); return f;
}

__global__ void k_init() {
    if (threadIdx.x < 4) g_grp[threadIdx.x * 32] = 0;
}

// ---------------- decoder x-projection ----------------
__global__ void k_dec_xproj(const float* __restrict__ emb_tgt,
                            const float* __restrict__ Wl,
                            const float* __restrict__ bias) {
    __shared__ float s_emb[E_];
    int v = blockIdx.y;
    int col = blockIdx.x * 256 + threadIdx.x;
    s_emb[threadIdx.x]       = emb_tgt[v * E_ + threadIdx.x];
    s_emb[256 + threadIdx.x] = emb_tgt[v * E_ + 256 + threadIdx.x];
    __syncthreads();
    float acc = bias[col];
#pragma unroll 8
    for (int k = 0; k < E_; ++k) acc += s_emb[k] * Wl[k * G4H + col];
    g_dec_xw[v * G4H + col] = acc;
}

// ---------------- encoder x-projection: 128x128 tile, row-pair FFMA2 ----------------
__global__ void __launch_bounds__(256)
k_enc_xproj(const int* __restrict__ src, const float* __restrict__ emb,
            const float* __restrict__ Wl, const float* __restrict__ bias) {
    __shared__ float As[2][16][132];
    __shared__ float Bs[2][16][128];
    __shared__ int s_tok[128];
    int tid = threadIdx.x;
    int col0 = blockIdx.x * 128, rg0 = blockIdx.y * 128;
    if (tid < 128) {
        int rg = rg0 + tid;
        s_tok[tid] = src[(rg & 63) * T_ + (rg >> 6)];
    }
    __syncthreads();

    int ty = tid >> 4, tx = tid & 15;
    int ar[2], akq[2], bkk[2], bc4[2];
#pragma unroll
    for (int i = 0; i < 2; ++i) {
        int idx4 = tid * 2 + i;
        ar[i] = idx4 >> 2; akq[i] = (idx4 & 3) * 4;
        bkk[i] = idx4 >> 5; bc4[i] = (idx4 & 31) * 4;
    }

    unsigned long long acc[4][8] = {};
    float4 ra[2], rb[2];

#pragma unroll
    for (int i = 0; i < 2; ++i) {
        ra[i] = *(const float4*)(emb + (long)s_tok[ar[i]] * E_ + akq[i]);
        rb[i] = *(const float4*)(Wl + (long)bkk[i] * G4H + col0 + bc4[i]);
    }
#pragma unroll
    for (int i = 0; i < 2; ++i) {
        As[0][akq[i] + 0][ar[i]] = ra[i].x;
        As[0][akq[i] + 1][ar[i]] = ra[i].y;
        As[0][akq[i] + 2][ar[i]] = ra[i].z;
        As[0][akq[i] + 3][ar[i]] = ra[i].w;
        *(float4*)&Bs[0][bkk[i]][bc4[i]] = rb[i];
    }
    __syncthreads();

    for (int p = 0; p < 32; ++p) {
        int buf = p & 1;
        if (p < 31) {
            int k0 = (p + 1) * 16;
#pragma unroll
            for (int i = 0; i < 2; ++i) {
                ra[i] = *(const float4*)(emb + (long)s_tok[ar[i]] * E_ + k0 + akq[i]);
                rb[i] = *(const float4*)(Wl + (long)(k0 + bkk[i]) * G4H + col0 + bc4[i]);
            }
        }
#pragma unroll
        for (int kk = 0; kk < 16; ++kk) {
            float4 a0 = *(const float4*)&As[buf][kk][ty * 8];
            float4 a1 = *(const float4*)&As[buf][kk][ty * 8 + 4];
            float4 b0 = *(const float4*)&Bs[buf][kk][tx * 8];
            float4 b1 = *(const float4*)&Bs[buf][kk][tx * 8 + 4];
            unsigned long long pa[4], pb[8];
            pa[0] = packab(a0.x, a0.y); pa[1] = packab(a0.z, a0.w);
            pa[2] = packab(a1.x, a1.y); pa[3] = packab(a1.z, a1.w);
            pb[0] = pack2(b0.x); pb[1] = pack2(b0.y); pb[2] = pack2(b0.z); pb[3] = pack2(b0.w);
            pb[4] = pack2(b1.x); pb[5] = pack2(b1.y); pb[6] = pack2(b1.z); pb[7] = pack2(b1.w);
#pragma unroll
            for (int rp = 0; rp < 4; ++rp)
#pragma unroll
                for (int c = 0; c < 8; ++c)
                    fma2(acc[rp][c], pa[rp], pb[c]);
        }
        if (p < 31) {
            int nb = buf ^ 1;
#pragma unroll
            for (int i = 0; i < 2; ++i) {
                As[nb][akq[i] + 0][ar[i]] = ra[i].x;
                As[nb][akq[i] + 1][ar[i]] = ra[i].y;
                As[nb][akq[i] + 2][ar[i]] = ra[i].z;
                As[nb][akq[i] + 3][ar[i]] = ra[i].w;
                *(float4*)&Bs[nb][bkk[i]][bc4[i]] = rb[i];
            }
            __syncthreads();
        }
    }

#pragma unroll
    for (int rp = 0; rp < 4; ++rp) {
        int r0 = rg0 + ty * 8 + rp * 2;
#pragma unroll
        for (int c = 0; c < 8; ++c) {
            float2 v = unpack2(acc[rp][c]);
            int col = col0 + tx * 8 + c;
            float b = bias[col];
            g_zx_enc[(long)r0 * G4H + col]       = v.x + b;
            g_zx_enc[(long)(r0 + 1) * G4H + col] = v.y + b;
        }
    }
}

// ---------------- persistent HMMA LSTM (staged producer-group waits) ----------------
__global__ void __launch_bounds__(NTHR, 1)
k_lstm_mma(const float* __restrict__ Wl, const int* __restrict__ tgt) {
    extern __shared__ char sm[];
    uint32_t smb = (uint32_t)__cvta_generic_to_shared(sm);
    float* zp0  = (float*)(sm + SM_Z);
    float* zp1  = (float*)(sm + SM_Z + ZPLANE);
    float* sdec = (float*)(sm + SM_SDEC);
    int*   stok = (int*)(sm + SM_STOK);
    int tid = threadIdx.x, wid = tid >> 5, lane = tid & 31;
    int cta = blockIdx.x;
    int j0 = cta * 8;

    // one-time: W single bf16 plane into SMEM (32 n-rows x 1024 k)
#pragma unroll 4
    for (int i = 0; i < 64; ++i) {
        int idx = i * NTHR + tid;          // 0..32767
        int n = idx >> 10, k = idx & 1023;
        int gcol = ((n >> 3) << 10) + j0 + (n & 7);
        float w = Wl[(E_ + k) * G4H + gcol];
        *(__nv_bfloat16*)(sm + SM_W + n * WPITCH + k * 2) = __float2bfloat16(w);
    }
#pragma unroll
    for (int i = 0; i < 4; ++i) {
        int idx = i * NTHR + tid;
        int v = idx >> 5, c = idx & 31;
        sdec[idx] = g_dec_xw[v * G4H + ((c >> 3) << 10) + j0 + (c & 7)];
    }
    __syncthreads();

    int m0 = (wid & 3) * 16, n0 = ((wid >> 2) & 1) * 16, ks = (wid >> 3) & 1;
    float* zpm = ks ? zp1 : zp0;
    uint32_t aoff = (uint32_t)((m0 + ((lane >> 3) & 1) * 8 + (lane & 7)) * APITCH +
                               (lane >> 4) * 16);
    uint32_t boff = smb + SM_W +
                    (uint32_t)((n0 + ((lane >> 3) & 1) * 8 + (lane & 7)) * WPITCH +
                               (lane >> 4) * 16);
    uint32_t abase[2] = { smb + SM_A0, smb + SM_A1 };

    int gb = tid >> 1, gjj = (tid & 1) * 4;
    float cr[4] = {0.f, 0.f, 0.f, 0.f};

    for (int t = 0; t < 2 * T_; ++t) {
        int dec = (t >= T_);
        const __nv_bfloat16* hp = &g_hbf[t & 1][0][0];
        if (dec && tid < 64) stok[tid] = tgt[tid * T_ + (t - T_)];

        float acc0[4] = {}, acc1[4] = {};

        if (t > 0) {
            unsigned tgtc = (unsigned)t * 32;
            // wait producer-group 0, then preload chunk 0 (k=0..255)
            if (tid == 0) {
                while (*((volatile unsigned*)&g_grp[0]) < tgtc) {}
                __threadfence();
            }
            __syncthreads();
#pragma unroll
            for (int i = 0; i < 4; ++i) {
                int idx = i * NTHR + tid;
                int r = idx >> 5, seg = idx & 31;
                cpasync16(abase[0] + (uint32_t)(r * APITCH + seg * 16),
                          hp + r * H_ + seg * 8);
            }
            asm volatile("cp.async.commit_group;");
            if (tid == 0) {
                while (*((volatile unsigned*)&g_grp[32]) < tgtc) {}
                __threadfence();
            }
            __syncthreads();

            for (int p = 0; p < 4; ++p) {
                if (p < 3) {
                    int nb = (p + 1) & 1;
#pragma unroll
                    for (int i = 0; i < 4; ++i) {
                        int idx = i * NTHR + tid;
                        int r = idx >> 5, seg = idx & 31;
                        cpasync16(abase[nb] + (uint32_t)(r * APITCH + seg * 16),
                                  hp + r * H_ + (p + 1) * 256 + seg * 8);
                    }
                    asm volatile("cp.async.commit_group;");
                    asm volatile("cp.async.wait_group 1;");
                    if (tid == 0 && p < 2) {   // poll group p+2 before its issue next iter
                        while (*((volatile unsigned*)&g_grp[(p + 2) * 32]) < tgtc) {}
                        __threadfence();
                    }
                } else {
                    asm volatile("cp.async.wait_group 0;");
                }
                __syncthreads();

                uint32_t ab = abase[p & 1] + aoff + (uint32_t)(ks * 256);
                uint32_t bb = boff + (uint32_t)(p * 512 + ks * 256);
#pragma unroll
                for (int i = 0; i < 8; ++i) {
                    uint32_t off = (uint32_t)(i * 32);
                    uint32_t ah[4], bh[4];
                    ldsm4(ah, ab + off);
                    ldsm4(bh, bb + off);
                    mma16816(acc0, ah, bh[0], bh[2]);
                    mma16816(acc1, ah, bh[1], bh[3]);
                }
                __syncthreads();
            }

            // stage partial z into this K-half's plane (aliases A0, now dead)
            int g = lane >> 2, tg = lane & 3;
            float* z0 = zpm + (m0 + g) * 34;
            float* z1 = zpm + (m0 + g + 8) * 34;
            z0[n0 + 2 * tg]     = acc0[0]; z0[n0 + 2 * tg + 1]     = acc0[1];
            z1[n0 + 2 * tg]     = acc0[2]; z1[n0 + 2 * tg + 1]     = acc0[3];
            z0[n0 + 8 + 2 * tg] = acc1[0]; z0[n0 + 8 + 2 * tg + 1] = acc1[1];
            z1[n0 + 8 + 2 * tg] = acc1[2]; z1[n0 + 8 + 2 * tg + 1] = acc1[3];
        }
        __syncthreads();

        // gates on 128 threads
        if (tid < 128) {
            float zv[4][4];
            if (!dec) {
                const float* zx = g_zx_enc + ((long)t * B_ + gb) * G4H + j0 + gjj;
#pragma unroll
                for (int q = 0; q < 4; ++q)
                    *(float4*)zv[q] = *(const float4*)(zx + q * 1024);
            } else {
                const float* xs = sdec + stok[gb] * 32 + gjj;
#pragma unroll
                for (int q = 0; q < 4; ++q)
                    *(float4*)zv[q] = *(const float4*)(xs + q * 8);
            }
            if (t > 0) {
#pragma unroll
                for (int q = 0; q < 4; ++q)
#pragma unroll
                    for (int l = 0; l < 4; ++l) {
                        int n = q * 8 + gjj + l;
                        zv[q][l] += zp0[gb * 34 + n] + zp1[gb * 34 + n];
                    }
            }
            float hh[4];
#pragma unroll
            for (int l = 0; l < 4; ++l) {
                float ig = sigf(zv[0][l]);
                float fg = sigf(zv[2][l] + 1.0f);    // forget_bias
                float og = sigf(zv[3][l]);
                cr[l] = fg * cr[l] + ig * tanhf(zv[1][l]);
                hh[l] = og * tanhf(cr[l]);
            }
            __nv_bfloat16 phi[4];
#pragma unroll
            for (int l = 0; l < 4; ++l) phi[l] = __float2bfloat16(hh[l]);
            *(uint2*)&g_hbf[(t + 1) & 1][gb][j0 + gjj] = *(uint2*)phi;
            if (dec) {
                float* hd = g_hs + ((long)(t - T_) * B_ + gb) * H_ + j0 + gjj;
                *(float4*)hd = make_float4(hh[0], hh[1], hh[2], hh[3]);
            }
        }

        // arrive only — no full-grid wait (staged waits gate next step's chunks)
        __syncthreads();
        if (tid == 0) {
            __threadfence();
            atomicAdd(&g_grp[(cta >> 5) * 32], 1u);
        }
    }
}

// ---------------- final projection + softmax ----------------
__global__ void k_proj_softmax(const float* __restrict__ Wp, const float* __restrict__ bp,
                               float* __restrict__ out) {
    __shared__ float h_t[32][33];
    __shared__ float w_t[32][VT];
    __shared__ float ls[32][VT + 1];
    __shared__ float s_inv[32];
    int tid = threadIdx.x;
    int rg0 = blockIdx.x * 32;
    int ty = tid >> 4, tx = tid & 15;
    float acc[2][4] = {};
    for (int k0 = 0; k0 < H_; k0 += 32) {
#pragma unroll
        for (int i = 0; i < 4; ++i) {
            int idx = i * 256 + tid;
            h_t[idx >> 5][idx & 31] = g_hs[(long)(rg0 + (idx >> 5)) * H_ + k0 + (idx & 31)];
        }
#pragma unroll
        for (int i = 0; i < 8; ++i) {
            int idx = i * 256 + tid;
            w_t[idx >> 6][idx & 63] = Wp[(k0 + (idx >> 6)) * VT + (idx & 63)];
        }
        __syncthreads();
#pragma unroll
        for (int kk = 0; kk < 32; ++kk) {
            float4 wv = *(const float4*)&w_t[kk][tx * 4];
            float a0 = h_t[ty * 2][kk], a1 = h_t[ty * 2 + 1][kk];
            acc[0][0] += a0 * wv.x; acc[0][1] += a0 * wv.y;
            acc[0][2] += a0 * wv.z; acc[0][3] += a0 * wv.w;
            acc[1][0] += a1 * wv.x; acc[1][1] += a1 * wv.y;
            acc[1][2] += a1 * wv.z; acc[1][3] += a1 * wv.w;
        }
        __syncthreads();
    }
#pragma unroll
    for (int i = 0; i < 2; ++i)
#pragma unroll
        for (int j = 0; j < 4; ++j)
            ls[ty * 2 + i][tx * 4 + j] = acc[i][j] + bp[tx * 4 + j];
    __syncthreads();
    if (tid < 32) {
        float m = -1e30f;
#pragma unroll 8
        for (int v = 0; v < VT; ++v) m = fmaxf(m, ls[tid][v]);
        float s = 0.f;
#pragma unroll 8
        for (int v = 0; v < VT; ++v) { float e = expf(ls[tid][v] - m); ls[tid][v] = e; s += e; }
        s_inv[tid] = 1.f / s;
    }
    __syncthreads();
#pragma unroll
    for (int i = 0; i < 8; ++i) {
        int idx = i * 256 + tid;
        int r = idx >> 6, v = idx & 63;
        int rg = rg0 + r;
        out[((rg & 63) * T_ + (rg >> 6)) * VT + v] = ls[r][v] * s_inv[r];
    }
}

extern "C" void kernel_launch(void* const* d_in, const int* in_sizes, int n_in,
                              void* d_out, int out_size) {
    const int*   src     = (const int*)d_in[0];
    const int*   tgt     = (const int*)d_in[1];
    const float* emb_src = (const float*)d_in[2];
    const float* emb_tgt = (const float*)d_in[3];
    const float* Wl      = (const float*)d_in[4];
    const float* bl      = (const float*)d_in[5];
    const float* Wp      = (const float*)d_in[6];
    const float* bp      = (const float*)d_in[7];
    float* out = (float*)d_out;
    (void)in_sizes; (void)n_in; (void)out_size;

    cudaFuncSetAttribute(k_lstm_mma, cudaFuncAttributeMaxDynamicSharedMemorySize, SM_TOT);

    k_init<<<1, 32>>>();
    k_dec_xproj<<<dim3(G4H / 256, VT), 256>>>(emb_tgt, Wl, bl);
    k_enc_xproj<<<dim3(G4H / 128, (T_ * B_) / 128), 256>>>(src, emb_src, Wl, bl);
    k_lstm_mma<<<NCTA, NTHR, SM_TOT>>>(Wl, tgt);
    k_proj_softmax<<<(T_ * B_) / 32, 256>>>(Wp, bp, out);
}

// round 14
// speedup vs baseline: 1.1192x; 1.1192x over previous
#include <cuda_runtime.h>
#include <cuda_bf16.h>
#include <math.h>
#include <stdint.h>

#define B_   64
#define T_   256
#define E_   512
#define H_   1024
#define G4H  4096
#define VT   64
#define NCTA 128
#define NTHR 512

__device__ float g_zx_enc[(long)T_ * B_ * G4H];
__device__ float g_dec_xw[VT * G4H];
__device__ __align__(16) __nv_bfloat16 g_hbf[2][B_][H_];   // [phase][b][k] bf16
__device__ float g_hs[(long)T_ * B_ * H_];
__device__ unsigned g_flag[NCTA * 32];   // one flag per 128B line
__device__ unsigned g_step;

// ---- persistent-LSTM SMEM layout (bytes) ----
#define WPITCH 2064            // 1032 bf16 per W row (1024 + 8 pad)
#define SM_W   0               // single plane, 32 n-rows = 66048
#define APITCH 528             // 264 bf16 per A row (256 + 8 pad)
#define SM_A0  66048
#define SM_A1  99840
#define SM_Z   66048           // z planes ALIAS A0 (A0 dead when z written)
#define ZPLANE 8704            // [64][34] f32
#define SM_SDEC 133632         // [64 tok][32] f32 = 8192
#define SM_STOK 141824         // [64] int = 256
#define SM_TOT  142080

__device__ __forceinline__ void cpasync16(uint32_t dst, const void* src) {
    asm volatile("cp.async.cg.shared.global [%0], [%1], 16;" :: "r"(dst), "l"(src));
}
__device__ __forceinline__ void ldsm4(uint32_t* f, uint32_t addr) {
    asm volatile("ldmatrix.sync.aligned.m8n8.x4.shared.b16 {%0,%1,%2,%3}, [%4];"
        : "=r"(f[0]), "=r"(f[1]), "=r"(f[2]), "=r"(f[3]) : "r"(addr));
}
__device__ __forceinline__ void mma16816(float* c, const uint32_t* a,
                                         uint32_t b0, uint32_t b1) {
    asm volatile("mma.sync.aligned.m16n8k16.row.col.f32.bf16.bf16.f32 "
        "{%0,%1,%2,%3}, {%4,%5,%6,%7}, {%8,%9}, {%0,%1,%2,%3};"
        : "+f"(c[0]), "+f"(c[1]), "+f"(c[2]), "+f"(c[3])
        : "r"(a[0]), "r"(a[1]), "r"(a[2]), "r"(a[3]), "r"(b0), "r"(b1));
}
__device__ __forceinline__ float sigf(float x) {
    return __fdividef(1.f, 1.f + __expf(-x));
}
__device__ __forceinline__ unsigned long long pack2(float x) {
    unsigned long long r; asm("mov.b64 %0, {%1,%1};" : "=l"(r) : "f"(x)); return r;
}
__device__ __forceinline__ unsigned long long packab(float a, float b) {
    unsigned long long r; asm("mov.b64 %0, {%1,%2};" : "=l"(r) : "f"(a), "f"(b)); return r;
}
__device__ __forceinline__ void fma2(unsigned long long& d, unsigned long long a,
                                     unsigned long long b) {
    asm("fma.rn.f32x2 %0, %1, %2, %0;" : "+l"(d) : "l"(a), "l"(b));
}
__device__ __forceinline__ float2 unpack2(unsigned long long v) {
    float2 f; asm("mov.b64 {%0,%1}, %2;" : "=f"(f.x), "=f"(f.y) : "l"(v)); return f;
}

__global__ void k_init() {
    if (threadIdx.x < NCTA) g_flag[threadIdx.x * 32] = 0;
    if (threadIdx.x == 0) g_step = 0;
}

// ---------------- decoder x-projection ----------------
__global__ void k_dec_xproj(const float* __restrict__ emb_tgt,
                            const float* __restrict__ Wl,
                            const float* __restrict__ bias) {
    __shared__ float s_emb[E_];
    int v = blockIdx.y;
    int col = blockIdx.x * 256 + threadIdx.x;
    s_emb[threadIdx.x]       = emb_tgt[v * E_ + threadIdx.x];
    s_emb[256 + threadIdx.x] = emb_tgt[v * E_ + 256 + threadIdx.x];
    __syncthreads();
    float acc = bias[col];
#pragma unroll 8
    for (int k = 0; k < E_; ++k) acc += s_emb[k] * Wl[k * G4H + col];
    g_dec_xw[v * G4H + col] = acc;
}

// ---------------- encoder x-projection: 128x128 tile, row-pair FFMA2 ----------------
__global__ void __launch_bounds__(256)
k_enc_xproj(const int* __restrict__ src, const float* __restrict__ emb,
            const float* __restrict__ Wl, const float* __restrict__ bias) {
    __shared__ float As[2][16][132];
    __shared__ float Bs[2][16][128];
    __shared__ int s_tok[128];
    int tid = threadIdx.x;
    int col0 = blockIdx.x * 128, rg0 = blockIdx.y * 128;
    if (tid < 128) {
        int rg = rg0 + tid;
        s_tok[tid] = src[(rg & 63) * T_ + (rg >> 6)];
    }
    __syncthreads();

    int ty = tid >> 4, tx = tid & 15;
    int ar[2], akq[2], bkk[2], bc4[2];
#pragma unroll
    for (int i = 0; i < 2; ++i) {
        int idx4 = tid * 2 + i;
        ar[i] = idx4 >> 2; akq[i] = (idx4 & 3) * 4;
        bkk[i] = idx4 >> 5; bc4[i] = (idx4 & 31) * 4;
    }

    unsigned long long acc[4][8] = {};
    float4 ra[2], rb[2];

#pragma unroll
    for (int i = 0; i < 2; ++i) {
        ra[i] = *(const float4*)(emb + (long)s_tok[ar[i]] * E_ + akq[i]);
        rb[i] = *(const float4*)(Wl + (long)bkk[i] * G4H + col0 + bc4[i]);
    }
#pragma unroll
    for (int i = 0; i < 2; ++i) {
        As[0][akq[i] + 0][ar[i]] = ra[i].x;
        As[0][akq[i] + 1][ar[i]] = ra[i].y;
        As[0][akq[i] + 2][ar[i]] = ra[i].z;
        As[0][akq[i] + 3][ar[i]] = ra[i].w;
        *(float4*)&Bs[0][bkk[i]][bc4[i]] = rb[i];
    }
    __syncthreads();

    for (int p = 0; p < 32; ++p) {
        int buf = p & 1;
        if (p < 31) {
            int k0 = (p + 1) * 16;
#pragma unroll
            for (int i = 0; i < 2; ++i) {
                ra[i] = *(const float4*)(emb + (long)s_tok[ar[i]] * E_ + k0 + akq[i]);
                rb[i] = *(const float4*)(Wl + (long)(k0 + bkk[i]) * G4H + col0 + bc4[i]);
            }
        }
#pragma unroll
        for (int kk = 0; kk < 16; ++kk) {
            float4 a0 = *(const float4*)&As[buf][kk][ty * 8];
            float4 a1 = *(const float4*)&As[buf][kk][ty * 8 + 4];
            float4 b0 = *(const float4*)&Bs[buf][kk][tx * 8];
            float4 b1 = *(const float4*)&Bs[buf][kk][tx * 8 + 4];
            unsigned long long pa[4], pb[8];
            pa[0] = packab(a0.x, a0.y); pa[1] = packab(a0.z, a0.w);
            pa[2] = packab(a1.x, a1.y); pa[3] = packab(a1.z, a1.w);
            pb[0] = pack2(b0.x); pb[1] = pack2(b0.y); pb[2] = pack2(b0.z); pb[3] = pack2(b0.w);
            pb[4] = pack2(b1.x); pb[5] = pack2(b1.y); pb[6] = pack2(b1.z); pb[7] = pack2(b1.w);
#pragma unroll
            for (int rp = 0; rp < 4; ++rp)
#pragma unroll
                for (int c = 0; c < 8; ++c)
                    fma2(acc[rp][c], pa[rp], pb[c]);
        }
        if (p < 31) {
            int nb = buf ^ 1;
#pragma unroll
            for (int i = 0; i < 2; ++i) {
                As[nb][akq[i] + 0][ar[i]] = ra[i].x;
                As[nb][akq[i] + 1][ar[i]] = ra[i].y;
                As[nb][akq[i] + 2][ar[i]] = ra[i].z;
                As[nb][akq[i] + 3][ar[i]] = ra[i].w;
                *(float4*)&Bs[nb][bkk[i]][bc4[i]] = rb[i];
            }
            __syncthreads();
        }
    }

#pragma unroll
    for (int rp = 0; rp < 4; ++rp) {
        int r0 = rg0 + ty * 8 + rp * 2;
#pragma unroll
        for (int c = 0; c < 8; ++c) {
            float2 v = unpack2(acc[rp][c]);
            int col = col0 + tx * 8 + c;
            float b = bias[col];
            g_zx_enc[(long)r0 * G4H + col]       = v.x + b;
            g_zx_enc[(long)(r0 + 1) * G4H + col] = v.y + b;
        }
    }
}

// ---------------- persistent HMMA LSTM (512 thr, K-split, bf16, k=256 chunks) ----------------
__global__ void __launch_bounds__(NTHR, 1)
k_lstm_mma(const float* __restrict__ Wl, const int* __restrict__ tgt) {
    extern __shared__ char sm[];
    uint32_t smb = (uint32_t)__cvta_generic_to_shared(sm);
    float* zp0  = (float*)(sm + SM_Z);
    float* zp1  = (float*)(sm + SM_Z + ZPLANE);
    float* sdec = (float*)(sm + SM_SDEC);
    int*   stok = (int*)(sm + SM_STOK);
    int tid = threadIdx.x, wid = tid >> 5, lane = tid & 31;
    int cta = blockIdx.x;
    int j0 = cta * 8;

    // one-time: W single bf16 plane into SMEM (32 n-rows x 1024 k)
#pragma unroll 4
    for (int i = 0; i < 64; ++i) {
        int idx = i * NTHR + tid;          // 0..32767
        int n = idx >> 10, k = idx & 1023;
        int gcol = ((n >> 3) << 10) + j0 + (n & 7);
        float w = Wl[(E_ + k) * G4H + gcol];
        *(__nv_bfloat16*)(sm + SM_W + n * WPITCH + k * 2) = __float2bfloat16(w);
    }
#pragma unroll
    for (int i = 0; i < 4; ++i) {
        int idx = i * NTHR + tid;
        int v = idx >> 5, c = idx & 31;
        sdec[idx] = g_dec_xw[v * G4H + ((c >> 3) << 10) + j0 + (c & 7)];
    }
    __syncthreads();

    int m0 = (wid & 3) * 16, n0 = ((wid >> 2) & 1) * 16, ks = (wid >> 3) & 1;
    float* zpm = ks ? zp1 : zp0;
    uint32_t aoff = (uint32_t)((m0 + ((lane >> 3) & 1) * 8 + (lane & 7)) * APITCH +
                               (lane >> 4) * 16);
    uint32_t boff = smb + SM_W +
                    (uint32_t)((n0 + ((lane >> 3) & 1) * 8 + (lane & 7)) * WPITCH +
                               (lane >> 4) * 16);
    uint32_t abase[2] = { smb + SM_A0, smb + SM_A1 };

    int gb = tid >> 1, gjj = (tid & 1) * 4;
    float cr[4] = {0.f, 0.f, 0.f, 0.f};

    for (int t = 0; t < 2 * T_; ++t) {
        int dec = (t >= T_);
        const __nv_bfloat16* hp = &g_hbf[t & 1][0][0];
        if (dec && tid < 64) stok[tid] = tgt[tid * T_ + (t - T_)];

        // encoder x-term prefetch into registers (hide L2 latency under GEMM)
        float zx4[4][4];
        if (tid < 128 && !dec) {
            const float* zx = g_zx_enc + ((long)t * B_ + gb) * G4H + j0 + gjj;
#pragma unroll
            for (int q = 0; q < 4; ++q)
                *(float4*)zx4[q] = *(const float4*)(zx + q * 1024);
        }

        float acc0[4] = {}, acc1[4] = {};

        if (t > 0) {
            // preload chunk 0 (k = 0..255, 32KB)
#pragma unroll
            for (int i = 0; i < 4; ++i) {
                int idx = i * NTHR + tid;
                int r = idx >> 5, seg = idx & 31;
                cpasync16(abase[0] + (uint32_t)(r * APITCH + seg * 16),
                          hp + r * H_ + seg * 8);
            }
            asm volatile("cp.async.commit_group;");

            for (int p = 0; p < 4; ++p) {
                if (p < 3) {
                    int nb = (p + 1) & 1;
#pragma unroll
                    for (int i = 0; i < 4; ++i) {
                        int idx = i * NTHR + tid;
                        int r = idx >> 5, seg = idx & 31;
                        cpasync16(abase[nb] + (uint32_t)(r * APITCH + seg * 16),
                                  hp + r * H_ + (p + 1) * 256 + seg * 8);
                    }
                    asm volatile("cp.async.commit_group;");
                    asm volatile("cp.async.wait_group 1;");
                } else {
                    asm volatile("cp.async.wait_group 0;");
                }
                __syncthreads();

                uint32_t ab = abase[p & 1] + aoff + (uint32_t)(ks * 256);
                uint32_t bb = boff + (uint32_t)(p * 512 + ks * 256);
#pragma unroll
                for (int i = 0; i < 8; ++i) {
                    uint32_t off = (uint32_t)(i * 32);
                    uint32_t ah[4], bh[4];
                    ldsm4(ah, ab + off);
                    ldsm4(bh, bb + off);
                    mma16816(acc0, ah, bh[0], bh[2]);
                    mma16816(acc1, ah, bh[1], bh[3]);
                }
                __syncthreads();
            }

            // stage partial z into this K-half's plane (aliases A0, now dead)
            int g = lane >> 2, tg = lane & 3;
            float* z0 = zpm + (m0 + g) * 34;
            float* z1 = zpm + (m0 + g + 8) * 34;
            z0[n0 + 2 * tg]     = acc0[0]; z0[n0 + 2 * tg + 1]     = acc0[1];
            z1[n0 + 2 * tg]     = acc0[2]; z1[n0 + 2 * tg + 1]     = acc0[3];
            z0[n0 + 8 + 2 * tg] = acc1[0]; z0[n0 + 8 + 2 * tg + 1] = acc1[1];
            z1[n0 + 8 + 2 * tg] = acc1[2]; z1[n0 + 8 + 2 * tg + 1] = acc1[3];
        }
        __syncthreads();

        // gates on 128 threads
        if (tid < 128) {
            float zv[4][4];
            if (!dec) {
#pragma unroll
                for (int q = 0; q < 4; ++q)
#pragma unroll
                    for (int l = 0; l < 4; ++l) zv[q][l] = zx4[q][l];
            } else {
                const float* xs = sdec + stok[gb] * 32 + gjj;
#pragma unroll
                for (int q = 0; q < 4; ++q)
                    *(float4*)zv[q] = *(const float4*)(xs + q * 8);
            }
            if (t > 0) {
#pragma unroll
                for (int q = 0; q < 4; ++q)
#pragma unroll
                    for (int l = 0; l < 4; ++l) {
                        int n = q * 8 + gjj + l;
                        zv[q][l] += zp0[gb * 34 + n] + zp1[gb * 34 + n];
                    }
            }
            float hh[4];
#pragma unroll
            for (int l = 0; l < 4; ++l) {
                float ig = sigf(zv[0][l]);
                float fg = sigf(zv[2][l] + 1.0f);    // forget_bias
                float og = sigf(zv[3][l]);
                cr[l] = fg * cr[l] + ig * tanhf(zv[1][l]);
                hh[l] = og * tanhf(cr[l]);
            }
            __nv_bfloat16 phi[4];
#pragma unroll
            for (int l = 0; l < 4; ++l) phi[l] = __float2bfloat16(hh[l]);
            *(uint2*)&g_hbf[(t + 1) & 1][gb][j0 + gjj] = *(uint2*)phi;
            if (dec) {
                float* hd = g_hs + ((long)(t - T_) * B_ + gb) * H_ + j0 + gjj;
                *(float4*)hd = make_float4(hh[0], hh[1], hh[2], hh[3]);
            }
        }

        // two-phase broadcast barrier: contention-free arrivals, CTA0 aggregates
        __syncthreads();
        unsigned tg1 = (unsigned)(t + 1);
        if (tid == 0) {
            __threadfence();
            *(volatile unsigned*)&g_flag[cta * 32] = tg1;
        }
        if (cta == 0) {
            if (tid < NCTA) {
                while (*(volatile unsigned*)&g_flag[tid * 32] < tg1) {}
            }
            __syncthreads();
            if (tid == 0) {
                __threadfence();
                *(volatile unsigned*)&g_step = tg1;
            }
        }
        if (tid == 0) {
            while (*(volatile unsigned*)&g_step < tg1) {}
            __threadfence();
        }
        __syncthreads();
    }
}

// ---------------- final projection + softmax ----------------
__global__ void k_proj_softmax(const float* __restrict__ Wp, const float* __restrict__ bp,
                               float* __restrict__ out) {
    __shared__ float h_t[32][33];
    __shared__ float w_t[32][VT];
    __shared__ float ls[32][VT + 1];
    __shared__ float s_inv[32];
    int tid = threadIdx.x;
    int rg0 = blockIdx.x * 32;
    int ty = tid >> 4, tx = tid & 15;
    float acc[2][4] = {};
    for (int k0 = 0; k0 < H_; k0 += 32) {
#pragma unroll
        for (int i = 0; i < 4; ++i) {
            int idx = i * 256 + tid;
            h_t[idx >> 5][idx & 31] = g_hs[(long)(rg0 + (idx >> 5)) * H_ + k0 + (idx & 31)];
        }
#pragma unroll
        for (int i = 0; i < 8; ++i) {
            int idx = i * 256 + tid;
            w_t[idx >> 6][idx & 63] = Wp[(k0 + (idx >> 6)) * VT + (idx & 63)];
        }
        __syncthreads();
#pragma unroll
        for (int kk = 0; kk < 32; ++kk) {
            float4 wv = *(const float4*)&w_t[kk][tx * 4];
            float a0 = h_t[ty * 2][kk], a1 = h_t[ty * 2 + 1][kk];
            acc[0][0] += a0 * wv.x; acc[0][1] += a0 * wv.y;
            acc[0][2] += a0 * wv.z; acc[0][3] += a0 * wv.w;
            acc[1][0] += a1 * wv.x; acc[1][1] += a1 * wv.y;
            acc[1][2] += a1 * wv.z; acc[1][3] += a1 * wv.w;
        }
        __syncthreads();
    }
#pragma unroll
    for (int i = 0; i < 2; ++i)
#pragma unroll
        for (int j = 0; j < 4; ++j)
            ls[ty * 2 + i][tx * 4 + j] = acc[i][j] + bp[tx * 4 + j];
    __syncthreads();
    if (tid < 32) {
        float m = -1e30f;
#pragma unroll 8
        for (int v = 0; v < VT; ++v) m = fmaxf(m, ls[tid][v]);
        float s = 0.f;
#pragma unroll 8
        for (int v = 0; v < VT; ++v) { float e = expf(ls[tid][v] - m); ls[tid][v] = e; s += e; }
        s_inv[tid] = 1.f / s;
    }
    __syncthreads();
#pragma unroll
    for (int i = 0; i < 8; ++i) {
        int idx = i * 256 + tid;
        int r = idx >> 6, v = idx & 63;
        int rg = rg0 + r;
        out[((rg & 63) * T_ + (rg >> 6)) * VT + v] = ls[r][v] * s_inv[r];
    }
}

extern "C" void kernel_launch(void* const* d_in, const int* in_sizes, int n_in,
                              void* d_out, int out_size) {
    const int*   src     = (const int*)d_in[0];
    const int*   tgt     = (const int*)d_in[1];
    const float* emb_src = (const float*)d_in[2];
    const float* emb_tgt = (const float*)d_in[3];
    const float* Wl      = (const float*)d_in[4];
    const float* bl      = (const float*)d_in[5];
    const float* Wp      = (const float*)d_in[6];
    const float* bp      = (const float*)d_in[7];
    float* out = (float*)d_out;
    (void)in_sizes; (void)n_in; (void)out_size;

    cudaFuncSetAttribute(k_lstm_mma, cudaFuncAttributeMaxDynamicSharedMemorySize, SM_TOT);

    k_init<<<1, 128>>>();
    k_dec_xproj<<<dim3(G4H / 256, VT), 256>>>(emb_tgt, Wl, bl);
    k_enc_xproj<<<dim3(G4H / 128, (T_ * B_) / 128), 256>>>(src, emb_src, Wl, bl);
    k_lstm_mma<<<NCTA, NTHR, SM_TOT>>>(Wl, tgt);
    k_proj_softmax<<<(T_ * B_) / 32, 256>>>(Wp, bp, out);
}

// round 15
// speedup vs baseline: 1.1399x; 1.0186x over previous
#include <cuda_runtime.h>
#include <cuda_bf16.h>
#include <math.h>
#include <stdint.h>

#define B_   64
#define T_   256
#define E_   512
#define H_   1024
#define G4H  4096
#define VT   64
#define NCTA 64
#define NTHR 512

__device__ float g_zx_enc[(long)T_ * B_ * G4H];
__device__ float g_dec_xw[VT * G4H];
__device__ __align__(16) __nv_bfloat16 g_hbf[2][B_][H_];   // [phase][b][k] bf16
__device__ float g_hs[(long)T_ * B_ * H_];
__device__ unsigned g_cnt;

// ---- persistent-LSTM SMEM layout (bytes) ----
#define WPITCH 2064            // 1032 bf16 per W row (1024 + 8 pad)
#define SM_W   0               // 64 n-rows = 132096
#define APITCH 528             // 264 bf16 per A row (256 + 8 pad)
#define SM_A0  132096          // 64 rows = 33792
#define SM_A1  165888
#define SM_Z   132096          // z planes ALIAS A0/A1 (dead when z written)
#define ZPLANE 17408           // [64][68] f32
#define SM_SDEC 199680         // [64 tok][64] f32 = 16384
#define SM_STOK 216064         // [64] int = 256
#define SM_TOT  216320

__device__ __forceinline__ void cpasync16(uint32_t dst, const void* src) {
    asm volatile("cp.async.cg.shared.global [%0], [%1], 16;" :: "r"(dst), "l"(src));
}
__device__ __forceinline__ void ldsm4(uint32_t* f, uint32_t addr) {
    asm volatile("ldmatrix.sync.aligned.m8n8.x4.shared.b16 {%0,%1,%2,%3}, [%4];"
        : "=r"(f[0]), "=r"(f[1]), "=r"(f[2]), "=r"(f[3]) : "r"(addr));
}
__device__ __forceinline__ void mma16816(float* c, const uint32_t* a,
                                         uint32_t b0, uint32_t b1) {
    asm volatile("mma.sync.aligned.m16n8k16.row.col.f32.bf16.bf16.f32 "
        "{%0,%1,%2,%3}, {%4,%5,%6,%7}, {%8,%9}, {%0,%1,%2,%3};"
        : "+f"(c[0]), "+f"(c[1]), "+f"(c[2]), "+f"(c[3])
        : "r"(a[0]), "r"(a[1]), "r"(a[2]), "r"(a[3]), "r"(b0), "r"(b1));
}
__device__ __forceinline__ float sigf(float x) {
    return __fdividef(1.f, 1.f + __expf(-x));
}
__device__ __forceinline__ unsigned long long pack2(float x) {
    unsigned long long r; asm("mov.b64 %0, {%1,%1};" : "=l"(r) : "f"(x)); return r;
}
__device__ __forceinline__ unsigned long long packab(float a, float b) {
    unsigned long long r; asm("mov.b64 %0, {%1,%2};" : "=l"(r) : "f"(a), "f"(b)); return r;
}
__device__ __forceinline__ void fma2(unsigned long long& d, unsigned long long a,
                                     unsigned long long b) {
    asm("fma.rn.f32x2 %0, %1, %2, %0;" : "+l"(d) : "l"(a), "l"(b));
}
__device__ __forceinline__ float2 unpack2(unsigned long long v) {
    float2 f; asm("mov.b64 {%0,%1}, %2;" : "=f"(f.x), "=f"(f.y) : "l"(v)); return f;
}

__global__ void k_init() { if (blockIdx.x == 0 && threadIdx.x == 0) g_cnt = 0; }

// ---------------- decoder x-projection ----------------
__global__ void k_dec_xproj(const float* __restrict__ emb_tgt,
                            const float* __restrict__ Wl,
                            const float* __restrict__ bias) {
    __shared__ float s_emb[E_];
    int v = blockIdx.y;
    int col = blockIdx.x * 256 + threadIdx.x;
    s_emb[threadIdx.x]       = emb_tgt[v * E_ + threadIdx.x];
    s_emb[256 + threadIdx.x] = emb_tgt[v * E_ + 256 + threadIdx.x];
    __syncthreads();
    float acc = bias[col];
#pragma unroll 8
    for (int k = 0; k < E_; ++k) acc += s_emb[k] * Wl[k * G4H + col];
    g_dec_xw[v * G4H + col] = acc;
}

// ---------------- encoder x-projection: 128x128 tile, row-pair FFMA2 ----------------
__global__ void __launch_bounds__(256)
k_enc_xproj(const int* __restrict__ src, const float* __restrict__ emb,
            const float* __restrict__ Wl, const float* __restrict__ bias) {
    __shared__ float As[2][16][132];
    __shared__ float Bs[2][16][128];
    __shared__ int s_tok[128];
    int tid = threadIdx.x;
    int col0 = blockIdx.x * 128, rg0 = blockIdx.y * 128;
    if (tid < 128) {
        int rg = rg0 + tid;
        s_tok[tid] = src[(rg & 63) * T_ + (rg >> 6)];
    }
    __syncthreads();

    int ty = tid >> 4, tx = tid & 15;
    int ar[2], akq[2], bkk[2], bc4[2];
#pragma unroll
    for (int i = 0; i < 2; ++i) {
        int idx4 = tid * 2 + i;
        ar[i] = idx4 >> 2; akq[i] = (idx4 & 3) * 4;
        bkk[i] = idx4 >> 5; bc4[i] = (idx4 & 31) * 4;
    }

    unsigned long long acc[4][8] = {};
    float4 ra[2], rb[2];

#pragma unroll
    for (int i = 0; i < 2; ++i) {
        ra[i] = *(const float4*)(emb + (long)s_tok[ar[i]] * E_ + akq[i]);
        rb[i] = *(const float4*)(Wl + (long)bkk[i] * G4H + col0 + bc4[i]);
    }
#pragma unroll
    for (int i = 0; i < 2; ++i) {
        As[0][akq[i] + 0][ar[i]] = ra[i].x;
        As[0][akq[i] + 1][ar[i]] = ra[i].y;
        As[0][akq[i] + 2][ar[i]] = ra[i].z;
        As[0][akq[i] + 3][ar[i]] = ra[i].w;
        *(float4*)&Bs[0][bkk[i]][bc4[i]] = rb[i];
    }
    __syncthreads();

    for (int p = 0; p < 32; ++p) {
        int buf = p & 1;
        if (p < 31) {
            int k0 = (p + 1) * 16;
#pragma unroll
            for (int i = 0; i < 2; ++i) {
                ra[i] = *(const float4*)(emb + (long)s_tok[ar[i]] * E_ + k0 + akq[i]);
                rb[i] = *(const float4*)(Wl + (long)(k0 + bkk[i]) * G4H + col0 + bc4[i]);
            }
        }
#pragma unroll
        for (int kk = 0; kk < 16; ++kk) {
            float4 a0 = *(const float4*)&As[buf][kk][ty * 8];
            float4 a1 = *(const float4*)&As[buf][kk][ty * 8 + 4];
            float4 b0 = *(const float4*)&Bs[buf][kk][tx * 8];
            float4 b1 = *(const float4*)&Bs[buf][kk][tx * 8 + 4];
            unsigned long long pa[4], pb[8];
            pa[0] = packab(a0.x, a0.y); pa[1] = packab(a0.z, a0.w);
            pa[2] = packab(a1.x, a1.y); pa[3] = packab(a1.z, a1.w);
            pb[0] = pack2(b0.x); pb[1] = pack2(b0.y); pb[2] = pack2(b0.z); pb[3] = pack2(b0.w);
            pb[4] = pack2(b1.x); pb[5] = pack2(b1.y); pb[6] = pack2(b1.z); pb[7] = pack2(b1.w);
#pragma unroll
            for (int rp = 0; rp < 4; ++rp)
#pragma unroll
                for (int c = 0; c < 8; ++c)
                    fma2(acc[rp][c], pa[rp], pb[c]);
        }
        if (p < 31) {
            int nb = buf ^ 1;
#pragma unroll
            for (int i = 0; i < 2; ++i) {
                As[nb][akq[i] + 0][ar[i]] = ra[i].x;
                As[nb][akq[i] + 1][ar[i]] = ra[i].y;
                As[nb][akq[i] + 2][ar[i]] = ra[i].z;
                As[nb][akq[i] + 3][ar[i]] = ra[i].w;
                *(float4*)&Bs[nb][bkk[i]][bc4[i]] = rb[i];
            }
            __syncthreads();
        }
    }

#pragma unroll
    for (int rp = 0; rp < 4; ++rp) {
        int r0 = rg0 + ty * 8 + rp * 2;
#pragma unroll
        for (int c = 0; c < 8; ++c) {
            float2 v = unpack2(acc[rp][c]);
            int col = col0 + tx * 8 + c;
            float b = bias[col];
            g_zx_enc[(long)r0 * G4H + col]       = v.x + b;
            g_zx_enc[(long)(r0 + 1) * G4H + col] = v.y + b;
        }
    }
}

// ---------------- persistent HMMA LSTM: 64 CTAs x 16 h-indices (N=64) ----------------
__global__ void __launch_bounds__(NTHR, 1)
k_lstm_mma(const float* __restrict__ Wl, const int* __restrict__ tgt) {
    extern __shared__ char sm[];
    uint32_t smb = (uint32_t)__cvta_generic_to_shared(sm);
    float* zp0  = (float*)(sm + SM_Z);
    float* zp1  = (float*)(sm + SM_Z + ZPLANE);
    float* sdec = (float*)(sm + SM_SDEC);
    int*   stok = (int*)(sm + SM_STOK);
    int tid = threadIdx.x, wid = tid >> 5, lane = tid & 31;
    int cta = blockIdx.x;
    int j0 = cta * 16;

    // one-time: W bf16 plane (64 n-rows x 1024 k)
#pragma unroll 4
    for (int i = 0; i < 128; ++i) {
        int idx = i * NTHR + tid;          // 0..65535
        int n = idx >> 10, k = idx & 1023;
        int gcol = ((n >> 4) << 10) + j0 + (n & 15);
        float w = Wl[(E_ + k) * G4H + gcol];
        *(__nv_bfloat16*)(sm + SM_W + n * WPITCH + k * 2) = __float2bfloat16(w);
    }
    // one-time: decoder x-term table [64 tok][64 cols]
#pragma unroll
    for (int i = 0; i < 8; ++i) {
        int idx = i * NTHR + tid;
        int v = idx >> 6, c = idx & 63;
        sdec[idx] = g_dec_xw[v * G4H + ((c >> 4) << 10) + j0 + (c & 15)];
    }
    __syncthreads();

    // warp tiling: 4 M-tiles x 2 N-tiles(32) x 2 K-halves
    int m0 = (wid & 3) * 16, n0 = ((wid >> 2) & 1) * 32, ks = (wid >> 3) & 1;
    float* zpm = ks ? zp1 : zp0;
    uint32_t aoff = (uint32_t)((m0 + ((lane >> 3) & 1) * 8 + (lane & 7)) * APITCH +
                               (lane >> 4) * 16);
    uint32_t boff = smb + SM_W +
                    (uint32_t)((n0 + ((lane >> 3) & 1) * 8 + (lane & 7)) * WPITCH +
                               (lane >> 4) * 16);
    uint32_t abase[2] = { smb + SM_A0, smb + SM_A1 };

    // gate threads: tid<256, thread owns (b = tid>>2, 4 h-idx at (tid&3)*4)
    int gb = tid >> 2, gjj = (tid & 3) * 4;
    float cr[4] = {0.f, 0.f, 0.f, 0.f};

    for (int t = 0; t < 2 * T_; ++t) {
        int dec = (t >= T_);
        const __nv_bfloat16* hp = &g_hbf[t & 1][0][0];
        if (dec && tid < 64) stok[tid] = tgt[tid * T_ + (t - T_)];

        // encoder x-term prefetch into registers
        float zx4[4][4];
        if (tid < 256 && !dec) {
            const float* zx = g_zx_enc + ((long)t * B_ + gb) * G4H + j0 + gjj;
#pragma unroll
            for (int q = 0; q < 4; ++q)
                *(float4*)zx4[q] = *(const float4*)(zx + q * 1024);
        }

        float accA0[4] = {}, accA1[4] = {}, accB0[4] = {}, accB1[4] = {};

        if (t > 0) {
            // preload chunk 0 (k = 0..255, 32KB)
#pragma unroll
            for (int i = 0; i < 4; ++i) {
                int idx = i * NTHR + tid;
                int r = idx >> 5, seg = idx & 31;
                cpasync16(abase[0] + (uint32_t)(r * APITCH + seg * 16),
                          hp + r * H_ + seg * 8);
            }
            asm volatile("cp.async.commit_group;");

            for (int p = 0; p < 4; ++p) {
                if (p < 3) {
                    int nb = (p + 1) & 1;
#pragma unroll
                    for (int i = 0; i < 4; ++i) {
                        int idx = i * NTHR + tid;
                        int r = idx >> 5, seg = idx & 31;
                        cpasync16(abase[nb] + (uint32_t)(r * APITCH + seg * 16),
                                  hp + r * H_ + (p + 1) * 256 + seg * 8);
                    }
                    asm volatile("cp.async.commit_group;");
                    asm volatile("cp.async.wait_group 1;");
                } else {
                    asm volatile("cp.async.wait_group 0;");
                }
                __syncthreads();

                uint32_t ab = abase[p & 1] + aoff + (uint32_t)(ks * 256);
                uint32_t bb = boff + (uint32_t)(p * 512 + ks * 256);
#pragma unroll
                for (int i = 0; i < 8; ++i) {
                    uint32_t off = (uint32_t)(i * 32);
                    uint32_t ah[4], bh[4], bg[4];
                    ldsm4(ah, ab + off);
                    ldsm4(bh, bb + off);
                    ldsm4(bg, bb + (uint32_t)(16 * WPITCH) + off);
                    mma16816(accA0, ah, bh[0], bh[2]);
                    mma16816(accA1, ah, bh[1], bh[3]);
                    mma16816(accB0, ah, bg[0], bg[2]);
                    mma16816(accB1, ah, bg[1], bg[3]);
                }
                __syncthreads();
            }

            // stage partial z (aliases A0/A1, both dead now)
            int g = lane >> 2, tg = lane & 3;
            float* z0 = zpm + (m0 + g) * 68;
            float* z1 = zpm + (m0 + g + 8) * 68;
            z0[n0 + 2 * tg]      = accA0[0]; z0[n0 + 2 * tg + 1]      = accA0[1];
            z1[n0 + 2 * tg]      = accA0[2]; z1[n0 + 2 * tg + 1]      = accA0[3];
            z0[n0 + 8 + 2 * tg]  = accA1[0]; z0[n0 + 8 + 2 * tg + 1]  = accA1[1];
            z1[n0 + 8 + 2 * tg]  = accA1[2]; z1[n0 + 8 + 2 * tg + 1]  = accA1[3];
            z0[n0 + 16 + 2 * tg] = accB0[0]; z0[n0 + 16 + 2 * tg + 1] = accB0[1];
            z1[n0 + 16 + 2 * tg] = accB0[2]; z1[n0 + 16 + 2 * tg + 1] = accB0[3];
            z0[n0 + 24 + 2 * tg] = accB1[0]; z0[n0 + 24 + 2 * tg + 1] = accB1[1];
            z1[n0 + 24 + 2 * tg] = accB1[2]; z1[n0 + 24 + 2 * tg + 1] = accB1[3];
        }
        __syncthreads();

        // gates on 256 threads
        if (tid < 256) {
            float zv[4][4];
            if (!dec) {
#pragma unroll
                for (int q = 0; q < 4; ++q)
#pragma unroll
                    for (int l = 0; l < 4; ++l) zv[q][l] = zx4[q][l];
            } else {
                const float* xs = sdec + stok[gb] * 64 + gjj;
#pragma unroll
                for (int q = 0; q < 4; ++q)
                    *(float4*)zv[q] = *(const float4*)(xs + q * 16);
            }
            if (t > 0) {
#pragma unroll
                for (int q = 0; q < 4; ++q)
#pragma unroll
                    for (int l = 0; l < 4; ++l) {
                        int n = q * 16 + gjj + l;
                        zv[q][l] += zp0[gb * 68 + n] + zp1[gb * 68 + n];
                    }
            }
            float hh[4];
#pragma unroll
            for (int l = 0; l < 4; ++l) {
                float ig = sigf(zv[0][l]);
                float fg = sigf(zv[2][l] + 1.0f);    // forget_bias
                float og = sigf(zv[3][l]);
                cr[l] = fg * cr[l] + ig * tanhf(zv[1][l]);
                hh[l] = og * tanhf(cr[l]);
            }
            __nv_bfloat16 phi[4];
#pragma unroll
            for (int l = 0; l < 4; ++l) phi[l] = __float2bfloat16(hh[l]);
            *(uint2*)&g_hbf[(t + 1) & 1][gb][j0 + gjj] = *(uint2*)phi;
            if (dec) {
                float* hd = g_hs + ((long)(t - T_) * B_ + gb) * H_ + j0 + gjj;
                *(float4*)hd = make_float4(hh[0], hh[1], hh[2], hh[3]);
            }
        }

        // grid barrier (atomic counter chain — r11 proven)
        __syncthreads();
        if (tid == 0) {
            __threadfence();
            unsigned target = (unsigned)(t + 1) * NCTA;
            atomicAdd(&g_cnt, 1u);
            while (*((volatile unsigned*)&g_cnt) < target) {}
            __threadfence();
        }
        __syncthreads();
    }
}

// ---------------- final projection + softmax ----------------
__global__ void k_proj_softmax(const float* __restrict__ Wp, const float* __restrict__ bp,
                               float* __restrict__ out) {
    __shared__ float h_t[32][33];
    __shared__ float w_t[32][VT];
    __shared__ float ls[32][VT + 1];
    __shared__ float s_inv[32];
    int tid = threadIdx.x;
    int rg0 = blockIdx.x * 32;
    int ty = tid >> 4, tx = tid & 15;
    float acc[2][4] = {};
    for (int k0 = 0; k0 < H_; k0 += 32) {
#pragma unroll
        for (int i = 0; i < 4; ++i) {
            int idx = i * 256 + tid;
            h_t[idx >> 5][idx & 31] = g_hs[(long)(rg0 + (idx >> 5)) * H_ + k0 + (idx & 31)];
        }
#pragma unroll
        for (int i = 0; i < 8; ++i) {
            int idx = i * 256 + tid;
            w_t[idx >> 6][idx & 63] = Wp[(k0 + (idx >> 6)) * VT + (idx & 63)];
        }
        __syncthreads();
#pragma unroll
        for (int kk = 0; kk < 32; ++kk) {
            float4 wv = *(const float4*)&w_t[kk][tx * 4];
            float a0 = h_t[ty * 2][kk], a1 = h_t[ty * 2 + 1][kk];
            acc[0][0] += a0 * wv.x; acc[0][1] += a0 * wv.y;
            acc[0][2] += a0 * wv.z; acc[0][3] += a0 * wv.w;
            acc[1][0] += a1 * wv.x; acc[1][1] += a1 * wv.y;
            acc[1][2] += a1 * wv.z; acc[1][3] += a1 * wv.w;
        }
        __syncthreads();
    }
#pragma unroll
    for (int i = 0; i < 2; ++i)
#pragma unroll
        for (int j = 0; j < 4; ++j)
            ls[ty * 2 + i][tx * 4 + j] = acc[i][j] + bp[tx * 4 + j];
    __syncthreads();
    if (tid < 32) {
        float m = -1e30f;
#pragma unroll 8
        for (int v = 0; v < VT; ++v) m = fmaxf(m, ls[tid][v]);
        float s = 0.f;
#pragma unroll 8
        for (int v = 0; v < VT; ++v) { float e = expf(ls[tid][v] - m); ls[tid][v] = e; s += e; }
        s_inv[tid] = 1.f / s;
    }
    __syncthreads();
#pragma unroll
    for (int i = 0; i < 8; ++i) {
        int idx = i * 256 + tid;
        int r = idx >> 6, v = idx & 63;
        int rg = rg0 + r;
        out[((rg & 63) * T_ + (rg >> 6)) * VT + v] = ls[r][v] * s_inv[r];
    }
}

extern "C" void kernel_launch(void* const* d_in, const int* in_sizes, int n_in,
                              void* d_out, int out_size) {
    const int*   src     = (const int*)d_in[0];
    const int*   tgt     = (const int*)d_in[1];
    const float* emb_src = (const float*)d_in[2];
    const float* emb_tgt = (const float*)d_in[3];
    const float* Wl      = (const float*)d_in[4];
    const float* bl      = (const float*)d_in[5];
    const float* Wp      = (const float*)d_in[6];
    const float* bp      = (const float*)d_in[7];
    float* out = (float*)d_out;
    (void)in_sizes; (void)n_in; (void)out_size;

    cudaFuncSetAttribute(k_lstm_mma, cudaFuncAttributeMaxDynamicSharedMemorySize, SM_TOT);

    k_init<<<1, 32>>>();
    k_dec_xproj<<<dim3(G4H / 256, VT), 256>>>(emb_tgt, Wl, bl);
    k_enc_xproj<<<dim3(G4H / 128, (T_ * B_) / 128), 256>>>(src, emb_src, Wl, bl);
    k_lstm_mma<<<NCTA, NTHR, SM_TOT>>>(Wl, tgt);
    k_proj_softmax<<<(T_ * B_) / 32, 256>>>(Wp, bp, out);
}

// round 16
// speedup vs baseline: 1.2825x; 1.1250x over previous
#include <cuda_runtime.h>
#include <cuda_bf16.h>
#include <math.h>
#include <stdint.h>

#define B_   64
#define T_   256
#define E_   512
#define H_   1024
#define G4H  4096
#define VT   64
#define NCTA 128
#define NTHR 512

__device__ float g_zx_enc[(long)T_ * B_ * G4H];
__device__ float g_dec_xw[VT * G4H];
__device__ __align__(16) __nv_bfloat16 g_hbf[2][B_][H_];   // [phase][b][k] bf16
__device__ float g_hs[(long)T_ * B_ * H_];
__device__ unsigned g_cnt;

// ---- persistent-LSTM SMEM layout (bytes) ----
#define WPITCH 2064            // 1032 bf16 per W row (1024 + 8 pad)
#define SM_W   0               // single plane, 32 n-rows = 66048
#define APITCH 528             // 264 bf16 per A row (256 + 8 pad)
#define SM_A0  66048           // 3 buffers x 33792
#define SM_A1  99840
#define SM_A2  133632
#define SM_Z   66048           // z planes ALIAS A0 (A0 dead when z written)
#define ZPLANE 8704            // [64][34] f32
#define SM_SDEC 167424         // [64 tok][32] f32 = 8192
#define SM_STOK 175616         // [64] int = 256
#define SM_TOT  175872

__device__ __forceinline__ void cpasync16(uint32_t dst, const void* src) {
    asm volatile("cp.async.cg.shared.global [%0], [%1], 16;" :: "r"(dst), "l"(src));
}
__device__ __forceinline__ void ldsm4(uint32_t* f, uint32_t addr) {
    asm volatile("ldmatrix.sync.aligned.m8n8.x4.shared.b16 {%0,%1,%2,%3}, [%4];"
        : "=r"(f[0]), "=r"(f[1]), "=r"(f[2]), "=r"(f[3]) : "r"(addr));
}
__device__ __forceinline__ void mma16816(float* c, const uint32_t* a,
                                         uint32_t b0, uint32_t b1) {
    asm volatile("mma.sync.aligned.m16n8k16.row.col.f32.bf16.bf16.f32 "
        "{%0,%1,%2,%3}, {%4,%5,%6,%7}, {%8,%9}, {%0,%1,%2,%3};"
        : "+f"(c[0]), "+f"(c[1]), "+f"(c[2]), "+f"(c[3])
        : "r"(a[0]), "r"(a[1]), "r"(a[2]), "r"(a[3]), "r"(b0), "r"(b1));
}
__device__ __forceinline__ float sigf(float x) {
    return __fdividef(1.f, 1.f + __expf(-x));
}
__device__ __forceinline__ unsigned long long pack2(float x) {
    unsigned long long r; asm("mov.b64 %0, {%1,%1};" : "=l"(r) : "f"(x)); return r;
}
__device__ __forceinline__ unsigned long long packab(float a, float b) {
    unsigned long long r; asm("mov.b64 %0, {%1,%2};" : "=l"(r) : "f"(a), "f"(b)); return r;
}
__device__ __forceinline__ void fma2(unsigned long long& d, unsigned long long a,
                                     unsigned long long b) {
    asm("fma.rn.f32x2 %0, %1, %2, %0;" : "+l"(d) : "l"(a), "l"(b));
}
__device__ __forceinline__ float2 unpack2(unsigned long long v) {
    float2 f; asm("mov.b64 {%0,%1}, %2;" : "=f"(f.x), "=f"(f.y) : "l"(v)); return f;
}

__global__ void k_init() { if (blockIdx.x == 0 && threadIdx.x == 0) g_cnt = 0; }

// ---------------- decoder x-projection ----------------
__global__ void k_dec_xproj(const float* __restrict__ emb_tgt,
                            const float* __restrict__ Wl,
                            const float* __restrict__ bias) {
    __shared__ float s_emb[E_];
    int v = blockIdx.y;
    int col = blockIdx.x * 256 + threadIdx.x;
    s_emb[threadIdx.x]       = emb_tgt[v * E_ + threadIdx.x];
    s_emb[256 + threadIdx.x] = emb_tgt[v * E_ + 256 + threadIdx.x];
    __syncthreads();
    float acc = bias[col];
#pragma unroll 8
    for (int k = 0; k < E_; ++k) acc += s_emb[k] * Wl[k * G4H + col];
    g_dec_xw[v * G4H + col] = acc;
}

// ---------------- encoder x-projection: 128x128 tile, row-pair FFMA2 ----------------
__global__ void __launch_bounds__(256)
k_enc_xproj(const int* __restrict__ src, const float* __restrict__ emb,
            const float* __restrict__ Wl, const float* __restrict__ bias) {
    __shared__ float As[2][16][132];
    __shared__ float Bs[2][16][128];
    __shared__ int s_tok[128];
    int tid = threadIdx.x;
    int col0 = blockIdx.x * 128, rg0 = blockIdx.y * 128;
    if (tid < 128) {
        int rg = rg0 + tid;
        s_tok[tid] = src[(rg & 63) * T_ + (rg >> 6)];
    }
    __syncthreads();

    int ty = tid >> 4, tx = tid & 15;
    int ar[2], akq[2], bkk[2], bc4[2];
#pragma unroll
    for (int i = 0; i < 2; ++i) {
        int idx4 = tid * 2 + i;
        ar[i] = idx4 >> 2; akq[i] = (idx4 & 3) * 4;
        bkk[i] = idx4 >> 5; bc4[i] = (idx4 & 31) * 4;
    }

    unsigned long long acc[4][8] = {};
    float4 ra[2], rb[2];

#pragma unroll
    for (int i = 0; i < 2; ++i) {
        ra[i] = *(const float4*)(emb + (long)s_tok[ar[i]] * E_ + akq[i]);
        rb[i] = *(const float4*)(Wl + (long)bkk[i] * G4H + col0 + bc4[i]);
    }
#pragma unroll
    for (int i = 0; i < 2; ++i) {
        As[0][akq[i] + 0][ar[i]] = ra[i].x;
        As[0][akq[i] + 1][ar[i]] = ra[i].y;
        As[0][akq[i] + 2][ar[i]] = ra[i].z;
        As[0][akq[i] + 3][ar[i]] = ra[i].w;
        *(float4*)&Bs[0][bkk[i]][bc4[i]] = rb[i];
    }
    __syncthreads();

    for (int p = 0; p < 32; ++p) {
        int buf = p & 1;
        if (p < 31) {
            int k0 = (p + 1) * 16;
#pragma unroll
            for (int i = 0; i < 2; ++i) {
                ra[i] = *(const float4*)(emb + (long)s_tok[ar[i]] * E_ + k0 + akq[i]);
                rb[i] = *(const float4*)(Wl + (long)(k0 + bkk[i]) * G4H + col0 + bc4[i]);
            }
        }
#pragma unroll
        for (int kk = 0; kk < 16; ++kk) {
            float4 a0 = *(const float4*)&As[buf][kk][ty * 8];
            float4 a1 = *(const float4*)&As[buf][kk][ty * 8 + 4];
            float4 b0 = *(const float4*)&Bs[buf][kk][tx * 8];
            float4 b1 = *(const float4*)&Bs[buf][kk][tx * 8 + 4];
            unsigned long long pa[4], pb[8];
            pa[0] = packab(a0.x, a0.y); pa[1] = packab(a0.z, a0.w);
            pa[2] = packab(a1.x, a1.y); pa[3] = packab(a1.z, a1.w);
            pb[0] = pack2(b0.x); pb[1] = pack2(b0.y); pb[2] = pack2(b0.z); pb[3] = pack2(b0.w);
            pb[4] = pack2(b1.x); pb[5] = pack2(b1.y); pb[6] = pack2(b1.z); pb[7] = pack2(b1.w);
#pragma unroll
            for (int rp = 0; rp < 4; ++rp)
#pragma unroll
                for (int c = 0; c < 8; ++c)
                    fma2(acc[rp][c], pa[rp], pb[c]);
        }
        if (p < 31) {
            int nb = buf ^ 1;
#pragma unroll
            for (int i = 0; i < 2; ++i) {
                As[nb][akq[i] + 0][ar[i]] = ra[i].x;
                As[nb][akq[i] + 1][ar[i]] = ra[i].y;
                As[nb][akq[i] + 2][ar[i]] = ra[i].z;
                As[nb][akq[i] + 3][ar[i]] = ra[i].w;
                *(float4*)&Bs[nb][bkk[i]][bc4[i]] = rb[i];
            }
            __syncthreads();
        }
    }

#pragma unroll
    for (int rp = 0; rp < 4; ++rp) {
        int r0 = rg0 + ty * 8 + rp * 2;
#pragma unroll
        for (int c = 0; c < 8; ++c) {
            float2 v = unpack2(acc[rp][c]);
            int col = col0 + tx * 8 + c;
            float b = bias[col];
            g_zx_enc[(long)r0 * G4H + col]       = v.x + b;
            g_zx_enc[(long)(r0 + 1) * G4H + col] = v.y + b;
        }
    }
}

// ---------------- persistent HMMA LSTM (r11 + 3-stage pipeline + cross-step zx prefetch) ----------------
__global__ void __launch_bounds__(NTHR, 1)
k_lstm_mma(const float* __restrict__ Wl, const int* __restrict__ tgt) {
    extern __shared__ char sm[];
    uint32_t smb = (uint32_t)__cvta_generic_to_shared(sm);
    float* zp0  = (float*)(sm + SM_Z);
    float* zp1  = (float*)(sm + SM_Z + ZPLANE);
    float* sdec = (float*)(sm + SM_SDEC);
    int*   stok = (int*)(sm + SM_STOK);
    int tid = threadIdx.x, wid = tid >> 5, lane = tid & 31;
    int cta = blockIdx.x;
    int j0 = cta * 8;

    // one-time: W single bf16 plane into SMEM (32 n-rows x 1024 k)
#pragma unroll 4
    for (int i = 0; i < 64; ++i) {
        int idx = i * NTHR + tid;          // 0..32767
        int n = idx >> 10, k = idx & 1023;
        int gcol = ((n >> 3) << 10) + j0 + (n & 7);
        float w = Wl[(E_ + k) * G4H + gcol];
        *(__nv_bfloat16*)(sm + SM_W + n * WPITCH + k * 2) = __float2bfloat16(w);
    }
#pragma unroll
    for (int i = 0; i < 4; ++i) {
        int idx = i * NTHR + tid;
        int v = idx >> 5, c = idx & 31;
        sdec[idx] = g_dec_xw[v * G4H + ((c >> 3) << 10) + j0 + (c & 7)];
    }
    __syncthreads();

    int m0 = (wid & 3) * 16, n0 = ((wid >> 2) & 1) * 16, ks = (wid >> 3) & 1;
    float* zpm = ks ? zp1 : zp0;
    uint32_t aoff = (uint32_t)((m0 + ((lane >> 3) & 1) * 8 + (lane & 7)) * APITCH +
                               (lane >> 4) * 16);
    uint32_t boff = smb + SM_W +
                    (uint32_t)((n0 + ((lane >> 3) & 1) * 8 + (lane & 7)) * WPITCH +
                               (lane >> 4) * 16);
    uint32_t abase[3] = { smb + SM_A0, smb + SM_A1, smb + SM_A2 };

    int gb = tid >> 1, gjj = (tid & 1) * 4;
    float cr[4] = {0.f, 0.f, 0.f, 0.f};

    // prefetch zx for step 0
    float zx4[4][4];
    if (tid < 128) {
        const float* zx = g_zx_enc + (long)gb * G4H + j0 + gjj;
#pragma unroll
        for (int q = 0; q < 4; ++q)
            *(float4*)zx4[q] = *(const float4*)(zx + q * 1024);
    }

    for (int t = 0; t < 2 * T_; ++t) {
        int dec = (t >= T_);
        const __nv_bfloat16* hp = &g_hbf[t & 1][0][0];
        if (dec && tid < 64) stok[tid] = tgt[tid * T_ + (t - T_)];

        float acc0[4] = {}, acc1[4] = {};

        if (t > 0) {
            // issue chunks 0 and 1 (two groups in flight)
#pragma unroll
            for (int c = 0; c < 2; ++c) {
#pragma unroll
                for (int i = 0; i < 4; ++i) {
                    int idx = i * NTHR + tid;
                    int r = idx >> 5, seg = idx & 31;
                    cpasync16(abase[c] + (uint32_t)(r * APITCH + seg * 16),
                              hp + r * H_ + c * 256 + seg * 8);
                }
                asm volatile("cp.async.commit_group;");
            }

#pragma unroll
            for (int p = 0; p < 4; ++p) {
                if (p < 3) asm volatile("cp.async.wait_group 1;");
                else       asm volatile("cp.async.wait_group 0;");
                __syncthreads();
                if (p < 2) {   // issue chunk p+2 into buf (p+2)%3
#pragma unroll
                    for (int i = 0; i < 4; ++i) {
                        int idx = i * NTHR + tid;
                        int r = idx >> 5, seg = idx & 31;
                        cpasync16(abase[(p + 2) % 3] + (uint32_t)(r * APITCH + seg * 16),
                                  hp + r * H_ + (p + 2) * 256 + seg * 8);
                    }
                    asm volatile("cp.async.commit_group;");
                }

                uint32_t ab = abase[p % 3] + aoff + (uint32_t)(ks * 256);
                uint32_t bb = boff + (uint32_t)(p * 512 + ks * 256);
#pragma unroll
                for (int i = 0; i < 8; ++i) {
                    uint32_t off = (uint32_t)(i * 32);
                    uint32_t ah[4], bh[4];
                    ldsm4(ah, ab + off);
                    ldsm4(bh, bb + off);
                    mma16816(acc0, ah, bh[0], bh[2]);
                    mma16816(acc1, ah, bh[1], bh[3]);
                }
            }
            __syncthreads();   // all MMA reads of buf0 done before z aliases it

            // stage partial z into this K-half's plane (aliases A0, now dead)
            int g = lane >> 2, tg = lane & 3;
            float* z0 = zpm + (m0 + g) * 34;
            float* z1 = zpm + (m0 + g + 8) * 34;
            z0[n0 + 2 * tg]     = acc0[0]; z0[n0 + 2 * tg + 1]     = acc0[1];
            z1[n0 + 2 * tg]     = acc0[2]; z1[n0 + 2 * tg + 1]     = acc0[3];
            z0[n0 + 8 + 2 * tg] = acc1[0]; z0[n0 + 8 + 2 * tg + 1] = acc1[1];
            z1[n0 + 8 + 2 * tg] = acc1[2]; z1[n0 + 8 + 2 * tg + 1] = acc1[3];
        }
        __syncthreads();

        // gates on 128 threads
        if (tid < 128) {
            float zv[4][4];
            if (!dec) {
#pragma unroll
                for (int q = 0; q < 4; ++q)
#pragma unroll
                    for (int l = 0; l < 4; ++l) zv[q][l] = zx4[q][l];
            } else {
                const float* xs = sdec + stok[gb] * 32 + gjj;
#pragma unroll
                for (int q = 0; q < 4; ++q)
                    *(float4*)zv[q] = *(const float4*)(xs + q * 8);
            }
            if (t > 0) {
#pragma unroll
                for (int q = 0; q < 4; ++q)
#pragma unroll
                    for (int l = 0; l < 4; ++l) {
                        int n = q * 8 + gjj + l;
                        zv[q][l] += zp0[gb * 34 + n] + zp1[gb * 34 + n];
                    }
            }
            float hh[4];
#pragma unroll
            for (int l = 0; l < 4; ++l) {
                float ig = sigf(zv[0][l]);
                float fg = sigf(zv[2][l] + 1.0f);    // forget_bias
                float og = sigf(zv[3][l]);
                cr[l] = fg * cr[l] + ig * tanhf(zv[1][l]);
                hh[l] = og * tanhf(cr[l]);
            }
            __nv_bfloat16 phi[4];
#pragma unroll
            for (int l = 0; l < 4; ++l) phi[l] = __float2bfloat16(hh[l]);
            *(uint2*)&g_hbf[(t + 1) & 1][gb][j0 + gjj] = *(uint2*)phi;
            if (dec) {
                float* hd = g_hs + ((long)(t - T_) * B_ + gb) * H_ + j0 + gjj;
                *(float4*)hd = make_float4(hh[0], hh[1], hh[2], hh[3]);
            }
            // cross-step zx prefetch: hide L2 latency under the barrier
            if (t + 1 < T_) {
                const float* zx = g_zx_enc + ((long)(t + 1) * B_ + gb) * G4H + j0 + gjj;
#pragma unroll
                for (int q = 0; q < 4; ++q)
                    *(float4*)zx4[q] = *(const float4*)(zx + q * 1024);
            }
        }

        // grid barrier (atomic counter chain — r11 proven)
        __syncthreads();
        if (tid == 0) {
            __threadfence();
            unsigned target = (unsigned)(t + 1) * NCTA;
            atomicAdd(&g_cnt, 1u);
            while (*((volatile unsigned*)&g_cnt) < target) {}
            __threadfence();
        }
        __syncthreads();
    }
}

// ---------------- final projection + softmax ----------------
__global__ void k_proj_softmax(const float* __restrict__ Wp, const float* __restrict__ bp,
                               float* __restrict__ out) {
    __shared__ float h_t[32][33];
    __shared__ float w_t[32][VT];
    __shared__ float ls[32][VT + 1];
    __shared__ float s_inv[32];
    int tid = threadIdx.x;
    int rg0 = blockIdx.x * 32;
    int ty = tid >> 4, tx = tid & 15;
    float acc[2][4] = {};
    for (int k0 = 0; k0 < H_; k0 += 32) {
#pragma unroll
        for (int i = 0; i < 4; ++i) {
            int idx = i * 256 + tid;
            h_t[idx >> 5][idx & 31] = g_hs[(long)(rg0 + (idx >> 5)) * H_ + k0 + (idx & 31)];
        }
#pragma unroll
        for (int i = 0; i < 8; ++i) {
            int idx = i * 256 + tid;
            w_t[idx >> 6][idx & 63] = Wp[(k0 + (idx >> 6)) * VT + (idx & 63)];
        }
        __syncthreads();
#pragma unroll
        for (int kk = 0; kk < 32; ++kk) {
            float4 wv = *(const float4*)&w_t[kk][tx * 4];
            float a0 = h_t[ty * 2][kk], a1 = h_t[ty * 2 + 1][kk];
            acc[0][0] += a0 * wv.x; acc[0][1] += a0 * wv.y;
            acc[0][2] += a0 * wv.z; acc[0][3] += a0 * wv.w;
            acc[1][0] += a1 * wv.x; acc[1][1] += a1 * wv.y;
            acc[1][2] += a1 * wv.z; acc[1][3] += a1 * wv.w;
        }
        __syncthreads();
    }
#pragma unroll
    for (int i = 0; i < 2; ++i)
#pragma unroll
        for (int j = 0; j < 4; ++j)
            ls[ty * 2 + i][tx * 4 + j] = acc[i][j] + bp[tx * 4 + j];
    __syncthreads();
    if (tid < 32) {
        float m = -1e30f;
#pragma unroll 8
        for (int v = 0; v < VT; ++v) m = fmaxf(m, ls[tid][v]);
        float s = 0.f;
#pragma unroll 8
        for (int v = 0; v < VT; ++v) { float e = expf(ls[tid][v] - m); ls[tid][v] = e; s += e; }
        s_inv[tid] = 1.f / s;
    }
    __syncthreads();
#pragma unroll
    for (int i = 0; i < 8; ++i) {
        int idx = i * 256 + tid;
        int r = idx >> 6, v = idx & 63;
        int rg = rg0 + r;
        out[((rg & 63) * T_ + (rg >> 6)) * VT + v] = ls[r][v] * s_inv[r];
    }
}

extern "C" void kernel_launch(void* const* d_in, const int* in_sizes, int n_in,
                              void* d_out, int out_size) {
    const int*   src     = (const int*)d_in[0];
    const int*   tgt     = (const int*)d_in[1];
    const float* emb_src = (const float*)d_in[2];
    const float* emb_tgt = (const float*)d_in[3];
    const float* Wl      = (const float*)d_in[4];
    const float* bl      = (const float*)d_in[5];
    const float* Wp      = (const float*)d_in[6];
    const float* bp      = (const float*)d_in[7];
    float* out = (float*)d_out;
    (void)in_sizes; (void)n_in; (void)out_size;

    cudaFuncSetAttribute(k_lstm_mma, cudaFuncAttributeMaxDynamicSharedMemorySize, SM_TOT);

    k_init<<<1, 32>>>();
    k_dec_xproj<<<dim3(G4H / 256, VT), 256>>>(emb_tgt, Wl, bl);
    k_enc_xproj<<<dim3(G4H / 128, (T_ * B_) / 128), 256>>>(src, emb_src, Wl, bl);
    k_lstm_mma<<<NCTA, NTHR, SM_TOT>>>(Wl, tgt);
    k_proj_softmax<<<(T_ * B_) / 32, 256>>>(Wp, bp, out);
}

// round 17
// speedup vs baseline: 1.3313x; 1.0381x over previous
#include <cuda_runtime.h>
#include <cuda_bf16.h>
#include <math.h>
#include <stdint.h>

#define B_   64
#define T_   256
#define E_   512
#define H_   1024
#define G4H  4096
#define VT   64
#define NCTA 128
#define NTHR 512

__device__ float g_zx_enc[(long)T_ * B_ * G4H];
__device__ float g_dec_xw[VT * G4H];
__device__ __align__(16) __nv_bfloat16 g_hbf[2][B_][H_];   // [phase][b][k] bf16
__device__ float g_hs[(long)T_ * B_ * H_];
__device__ unsigned g_cnt;

// ---- persistent-LSTM SMEM layout (bytes) ----
#define WPITCH 2064            // 1032 bf16 per W row (1024 + 8 pad)
#define SM_W   0               // single plane, 32 n-rows = 66048
#define APITCH 528             // 264 bf16 per A row (256 + 8 pad)
#define SM_A0  66048           // 3 buffers x 33792
#define SM_A1  99840
#define SM_A2  133632
#define SM_Z   66048           // z planes ALIAS A0 (A0 dead when z written)
#define ZPLANE 8704            // [64][34] f32
#define SM_SDEC 167424         // [64 tok][32] f32 = 8192
#define SM_STOK 175616         // [64] int = 256
#define SM_TOT  175872

__device__ __forceinline__ void cpasync16(uint32_t dst, const void* src) {
    asm volatile("cp.async.cg.shared.global [%0], [%1], 16;" :: "r"(dst), "l"(src));
}
__device__ __forceinline__ void ldsm4(uint32_t* f, uint32_t addr) {
    asm volatile("ldmatrix.sync.aligned.m8n8.x4.shared.b16 {%0,%1,%2,%3}, [%4];"
        : "=r"(f[0]), "=r"(f[1]), "=r"(f[2]), "=r"(f[3]) : "r"(addr));
}
__device__ __forceinline__ void mma16816(float* c, const uint32_t* a,
                                         uint32_t b0, uint32_t b1) {
    asm volatile("mma.sync.aligned.m16n8k16.row.col.f32.bf16.bf16.f32 "
        "{%0,%1,%2,%3}, {%4,%5,%6,%7}, {%8,%9}, {%0,%1,%2,%3};"
        : "+f"(c[0]), "+f"(c[1]), "+f"(c[2]), "+f"(c[3])
        : "r"(a[0]), "r"(a[1]), "r"(a[2]), "r"(a[3]), "r"(b0), "r"(b1));
}
__device__ __forceinline__ float sigf(float x) {
    return __fdividef(1.f, 1.f + __expf(-x));
}
__device__ __forceinline__ unsigned long long pack2(float x) {
    unsigned long long r; asm("mov.b64 %0, {%1,%1};" : "=l"(r) : "f"(x)); return r;
}
__device__ __forceinline__ unsigned long long packab(float a, float b) {
    unsigned long long r; asm("mov.b64 %0, {%1,%2};" : "=l"(r) : "f"(a), "f"(b)); return r;
}
__device__ __forceinline__ void fma2(unsigned long long& d, unsigned long long a,
                                     unsigned long long b) {
    asm("fma.rn.f32x2 %0, %1, %2, %0;" : "+l"(d) : "l"(a), "l"(b));
}
__device__ __forceinline__ float2 unpack2(unsigned long long v) {
    float2 f; asm("mov.b64 {%0,%1}, %2;" : "=f"(f.x), "=f"(f.y) : "l"(v)); return f;
}

__global__ void k_init() { if (blockIdx.x == 0 && threadIdx.x == 0) g_cnt = 0; }

// ---------------- decoder x-projection ----------------
__global__ void k_dec_xproj(const float* __restrict__ emb_tgt,
                            const float* __restrict__ Wl,
                            const float* __restrict__ bias) {
    __shared__ float s_emb[E_];
    int v = blockIdx.y;
    int col = blockIdx.x * 256 + threadIdx.x;
    s_emb[threadIdx.x]       = emb_tgt[v * E_ + threadIdx.x];
    s_emb[256 + threadIdx.x] = emb_tgt[v * E_ + 256 + threadIdx.x];
    __syncthreads();
    float acc = bias[col];
#pragma unroll 8
    for (int k = 0; k < E_; ++k) acc += s_emb[k] * Wl[k * G4H + col];
    g_dec_xw[v * G4H + col] = acc;
}

// ---------------- encoder x-projection: 128x128 tile, row-pair FFMA2 ----------------
__global__ void __launch_bounds__(256)
k_enc_xproj(const int* __restrict__ src, const float* __restrict__ emb,
            const float* __restrict__ Wl, const float* __restrict__ bias) {
    __shared__ float As[2][16][132];
    __shared__ float Bs[2][16][128];
    __shared__ int s_tok[128];
    int tid = threadIdx.x;
    int col0 = blockIdx.x * 128, rg0 = blockIdx.y * 128;
    if (tid < 128) {
        int rg = rg0 + tid;
        s_tok[tid] = src[(rg & 63) * T_ + (rg >> 6)];
    }
    __syncthreads();

    int ty = tid >> 4, tx = tid & 15;
    int ar[2], akq[2], bkk[2], bc4[2];
#pragma unroll
    for (int i = 0; i < 2; ++i) {
        int idx4 = tid * 2 + i;
        ar[i] = idx4 >> 2; akq[i] = (idx4 & 3) * 4;
        bkk[i] = idx4 >> 5; bc4[i] = (idx4 & 31) * 4;
    }

    unsigned long long acc[4][8] = {};
    float4 ra[2], rb[2];

#pragma unroll
    for (int i = 0; i < 2; ++i) {
        ra[i] = *(const float4*)(emb + (long)s_tok[ar[i]] * E_ + akq[i]);
        rb[i] = *(const float4*)(Wl + (long)bkk[i] * G4H + col0 + bc4[i]);
    }
#pragma unroll
    for (int i = 0; i < 2; ++i) {
        As[0][akq[i] + 0][ar[i]] = ra[i].x;
        As[0][akq[i] + 1][ar[i]] = ra[i].y;
        As[0][akq[i] + 2][ar[i]] = ra[i].z;
        As[0][akq[i] + 3][ar[i]] = ra[i].w;
        *(float4*)&Bs[0][bkk[i]][bc4[i]] = rb[i];
    }
    __syncthreads();

    for (int p = 0; p < 32; ++p) {
        int buf = p & 1;
        if (p < 31) {
            int k0 = (p + 1) * 16;
#pragma unroll
            for (int i = 0; i < 2; ++i) {
                ra[i] = *(const float4*)(emb + (long)s_tok[ar[i]] * E_ + k0 + akq[i]);
                rb[i] = *(const float4*)(Wl + (long)(k0 + bkk[i]) * G4H + col0 + bc4[i]);
            }
        }
#pragma unroll
        for (int kk = 0; kk < 16; ++kk) {
            float4 a0 = *(const float4*)&As[buf][kk][ty * 8];
            float4 a1 = *(const float4*)&As[buf][kk][ty * 8 + 4];
            float4 b0 = *(const float4*)&Bs[buf][kk][tx * 8];
            float4 b1 = *(const float4*)&Bs[buf][kk][tx * 8 + 4];
            unsigned long long pa[4], pb[8];
            pa[0] = packab(a0.x, a0.y); pa[1] = packab(a0.z, a0.w);
            pa[2] = packab(a1.x, a1.y); pa[3] = packab(a1.z, a1.w);
            pb[0] = pack2(b0.x); pb[1] = pack2(b0.y); pb[2] = pack2(b0.z); pb[3] = pack2(b0.w);
            pb[4] = pack2(b1.x); pb[5] = pack2(b1.y); pb[6] = pack2(b1.z); pb[7] = pack2(b1.w);
#pragma unroll
            for (int rp = 0; rp < 4; ++rp)
#pragma unroll
                for (int c = 0; c < 8; ++c)
                    fma2(acc[rp][c], pa[rp], pb[c]);
        }
        if (p < 31) {
            int nb = buf ^ 1;
#pragma unroll
            for (int i = 0; i < 2; ++i) {
                As[nb][akq[i] + 0][ar[i]] = ra[i].x;
                As[nb][akq[i] + 1][ar[i]] = ra[i].y;
                As[nb][akq[i] + 2][ar[i]] = ra[i].z;
                As[nb][akq[i] + 3][ar[i]] = ra[i].w;
                *(float4*)&Bs[nb][bkk[i]][bc4[i]] = rb[i];
            }
            __syncthreads();
        }
    }

#pragma unroll
    for (int rp = 0; rp < 4; ++rp) {
        int r0 = rg0 + ty * 8 + rp * 2;
#pragma unroll
        for (int c = 0; c < 8; ++c) {
            float2 v = unpack2(acc[rp][c]);
            int col = col0 + tx * 8 + c;
            float b = bias[col];
            g_zx_enc[(long)r0 * G4H + col]       = v.x + b;
            g_zx_enc[(long)(r0 + 1) * G4H + col] = v.y + b;
        }
    }
}

// ---------------- persistent HMMA LSTM (r16 + 512-thread gates + acq/rel barrier) ----------------
__global__ void __launch_bounds__(NTHR, 1)
k_lstm_mma(const float* __restrict__ Wl, const int* __restrict__ tgt) {
    extern __shared__ char sm[];
    uint32_t smb = (uint32_t)__cvta_generic_to_shared(sm);
    float* zp0  = (float*)(sm + SM_Z);
    float* zp1  = (float*)(sm + SM_Z + ZPLANE);
    float* sdec = (float*)(sm + SM_SDEC);
    int*   stok = (int*)(sm + SM_STOK);
    int tid = threadIdx.x, wid = tid >> 5, lane = tid & 31;
    int cta = blockIdx.x;
    int j0 = cta * 8;

    // one-time: W single bf16 plane into SMEM (32 n-rows x 1024 k)
#pragma unroll 4
    for (int i = 0; i < 64; ++i) {
        int idx = i * NTHR + tid;          // 0..32767
        int n = idx >> 10, k = idx & 1023;
        int gcol = ((n >> 3) << 10) + j0 + (n & 7);
        float w = Wl[(E_ + k) * G4H + gcol];
        *(__nv_bfloat16*)(sm + SM_W + n * WPITCH + k * 2) = __float2bfloat16(w);
    }
#pragma unroll
    for (int i = 0; i < 4; ++i) {
        int idx = i * NTHR + tid;
        int v = idx >> 5, c = idx & 31;
        sdec[idx] = g_dec_xw[v * G4H + ((c >> 3) << 10) + j0 + (c & 7)];
    }
    __syncthreads();

    int m0 = (wid & 3) * 16, n0 = ((wid >> 2) & 1) * 16, ks = (wid >> 3) & 1;
    float* zpm = ks ? zp1 : zp0;
    uint32_t aoff = (uint32_t)((m0 + ((lane >> 3) & 1) * 8 + (lane & 7)) * APITCH +
                               (lane >> 4) * 16);
    uint32_t boff = smb + SM_W +
                    (uint32_t)((n0 + ((lane >> 3) & 1) * 8 + (lane & 7)) * WPITCH +
                               (lane >> 4) * 16);
    uint32_t abase[3] = { smb + SM_A0, smb + SM_A1, smb + SM_A2 };

    // gate assignment: every thread owns (b = tid>>3, single h-index jj = tid&7)
    int gb = tid >> 3, gjj = tid & 7;
    float cr = 0.f;

    // prefetch zx for step 0 (4 gate columns, stride 1024)
    float zx4[4];
    {
        const float* zx = g_zx_enc + (long)gb * G4H + j0 + gjj;
#pragma unroll
        for (int q = 0; q < 4; ++q) zx4[q] = zx[q * 1024];
    }

    for (int t = 0; t < 2 * T_; ++t) {
        int dec = (t >= T_);
        const __nv_bfloat16* hp = &g_hbf[t & 1][0][0];
        if (dec && tid < 64) stok[tid] = tgt[tid * T_ + (t - T_)];

        float acc0[4] = {}, acc1[4] = {};

        if (t > 0) {
            // issue chunks 0 and 1 (two groups in flight)
#pragma unroll
            for (int c = 0; c < 2; ++c) {
#pragma unroll
                for (int i = 0; i < 4; ++i) {
                    int idx = i * NTHR + tid;
                    int r = idx >> 5, seg = idx & 31;
                    cpasync16(abase[c] + (uint32_t)(r * APITCH + seg * 16),
                              hp + r * H_ + c * 256 + seg * 8);
                }
                asm volatile("cp.async.commit_group;");
            }

#pragma unroll
            for (int p = 0; p < 4; ++p) {
                if (p < 3) asm volatile("cp.async.wait_group 1;");
                else       asm volatile("cp.async.wait_group 0;");
                __syncthreads();
                if (p < 2) {   // issue chunk p+2 into buf (p+2)%3
#pragma unroll
                    for (int i = 0; i < 4; ++i) {
                        int idx = i * NTHR + tid;
                        int r = idx >> 5, seg = idx & 31;
                        cpasync16(abase[(p + 2) % 3] + (uint32_t)(r * APITCH + seg * 16),
                                  hp + r * H_ + (p + 2) * 256 + seg * 8);
                    }
                    asm volatile("cp.async.commit_group;");
                }

                uint32_t ab = abase[p % 3] + aoff + (uint32_t)(ks * 256);
                uint32_t bb = boff + (uint32_t)(p * 512 + ks * 256);
#pragma unroll
                for (int i = 0; i < 8; ++i) {
                    uint32_t off = (uint32_t)(i * 32);
                    uint32_t ah[4], bh[4];
                    ldsm4(ah, ab + off);
                    ldsm4(bh, bb + off);
                    mma16816(acc0, ah, bh[0], bh[2]);
                    mma16816(acc1, ah, bh[1], bh[3]);
                }
            }
            __syncthreads();   // all MMA reads of buf0 done before z aliases it

            // stage partial z into this K-half's plane (aliases A0, now dead)
            int g = lane >> 2, tg = lane & 3;
            float* z0 = zpm + (m0 + g) * 34;
            float* z1 = zpm + (m0 + g + 8) * 34;
            z0[n0 + 2 * tg]     = acc0[0]; z0[n0 + 2 * tg + 1]     = acc0[1];
            z1[n0 + 2 * tg]     = acc0[2]; z1[n0 + 2 * tg + 1]     = acc0[3];
            z0[n0 + 8 + 2 * tg] = acc1[0]; z0[n0 + 8 + 2 * tg + 1] = acc1[1];
            z1[n0 + 8 + 2 * tg] = acc1[2]; z1[n0 + 8 + 2 * tg + 1] = acc1[3];
        }
        __syncthreads();

        // gates on all 512 threads (1 h-index each)
        {
            float zv[4];
            if (!dec) {
#pragma unroll
                for (int q = 0; q < 4; ++q) zv[q] = zx4[q];
            } else {
                const float* xs = sdec + stok[gb] * 32 + gjj;
#pragma unroll
                for (int q = 0; q < 4; ++q) zv[q] = xs[q * 8];
            }
            if (t > 0) {
#pragma unroll
                for (int q = 0; q < 4; ++q) {
                    int n = q * 8 + gjj;
                    zv[q] += zp0[gb * 34 + n] + zp1[gb * 34 + n];
                }
            }
            float ig = sigf(zv[0]);
            float fg = sigf(zv[2] + 1.0f);    // forget_bias
            float og = sigf(zv[3]);
            cr = fg * cr + ig * tanhf(zv[1]);
            float hv = og * tanhf(cr);
            g_hbf[(t + 1) & 1][gb][j0 + gjj] = __float2bfloat16(hv);
            if (dec)
                g_hs[((long)(t - T_) * B_ + gb) * H_ + j0 + gjj] = hv;
            // cross-step zx prefetch: hide L2 latency under the barrier
            if (t + 1 < T_) {
                const float* zx = g_zx_enc + ((long)(t + 1) * B_ + gb) * G4H + j0 + gjj;
#pragma unroll
                for (int q = 0; q < 4; ++q) zx4[q] = zx[q * 1024];
            }
        }

        // grid barrier (release atomic + acquire poll; no full MEMBAR)
        __syncthreads();
        if (tid == 0) {
            unsigned target = (unsigned)(t + 1) * NCTA;
            asm volatile("red.release.gpu.global.add.u32 [%0], 1;"
                         :: "l"(&g_cnt) : "memory");
            unsigned v;
            do {
                asm volatile("ld.acquire.gpu.global.u32 %0, [%1];"
                             : "=r"(v) : "l"(&g_cnt) : "memory");
            } while (v < target);
        }
        __syncthreads();
    }
}

// ---------------- final projection + softmax ----------------
__global__ void k_proj_softmax(const float* __restrict__ Wp, const float* __restrict__ bp,
                               float* __restrict__ out) {
    __shared__ float h_t[32][33];
    __shared__ float w_t[32][VT];
    __shared__ float ls[32][VT + 1];
    __shared__ float s_inv[32];
    int tid = threadIdx.x;
    int rg0 = blockIdx.x * 32;
    int ty = tid >> 4, tx = tid & 15;
    float acc[2][4] = {};
    for (int k0 = 0; k0 < H_; k0 += 32) {
#pragma unroll
        for (int i = 0; i < 4; ++i) {
            int idx = i * 256 + tid;
            h_t[idx >> 5][idx & 31] = g_hs[(long)(rg0 + (idx >> 5)) * H_ + k0 + (idx & 31)];
        }
#pragma unroll
        for (int i = 0; i < 8; ++i) {
            int idx = i * 256 + tid;
            w_t[idx >> 6][idx & 63] = Wp[(k0 + (idx >> 6)) * VT + (idx & 63)];
        }
        __syncthreads();
#pragma unroll
        for (int kk = 0; kk < 32; ++kk) {
            float4 wv = *(const float4*)&w_t[kk][tx * 4];
            float a0 = h_t[ty * 2][kk], a1 = h_t[ty * 2 + 1][kk];
            acc[0][0] += a0 * wv.x; acc[0][1] += a0 * wv.y;
            acc[0][2] += a0 * wv.z; acc[0][3] += a0 * wv.w;
            acc[1][0] += a1 * wv.x; acc[1][1] += a1 * wv.y;
            acc[1][2] += a1 * wv.z; acc[1][3] += a1 * wv.w;
        }
        __syncthreads();
    }
#pragma unroll
    for (int i = 0; i < 2; ++i)
#pragma unroll
        for (int j = 0; j < 4; ++j)
            ls[ty * 2 + i][tx * 4 + j] = acc[i][j] + bp[tx * 4 + j];
    __syncthreads();
    if (tid < 32) {
        float m = -1e30f;
#pragma unroll 8
        for (int v = 0; v < VT; ++v) m = fmaxf(m, ls[tid][v]);
        float s = 0.f;
#pragma unroll 8
        for (int v = 0; v < VT; ++v) { float e = expf(ls[tid][v] - m); ls[tid][v] = e; s += e; }
        s_inv[tid] = 1.f / s;
    }
    __syncthreads();
#pragma unroll
    for (int i = 0; i < 8; ++i) {
        int idx = i * 256 + tid;
        int r = idx >> 6, v = idx & 63;
        int rg = rg0 + r;
        out[((rg & 63) * T_ + (rg >> 6)) * VT + v] = ls[r][v] * s_inv[r];
    }
}

extern "C" void kernel_launch(void* const* d_in, const int* in_sizes, int n_in,
                              void* d_out, int out_size) {
    const int*   src     = (const int*)d_in[0];
    const int*   tgt     = (const int*)d_in[1];
    const float* emb_src = (const float*)d_in[2];
    const float* emb_tgt = (const float*)d_in[3];
    const float* Wl      = (const float*)d_in[4];
    const float* bl      = (const float*)d_in[5];
    const float* Wp      = (const float*)d_in[6];
    const float* bp      = (const float*)d_in[7];
    float* out = (float*)d_out;
    (void)in_sizes; (void)n_in; (void)out_size;

    cudaFuncSetAttribute(k_lstm_mma, cudaFuncAttributeMaxDynamicSharedMemorySize, SM_TOT);

    k_init<<<1, 32>>>();
    k_dec_xproj<<<dim3(G4H / 256, VT), 256>>>(emb_tgt, Wl, bl);
    k_enc_xproj<<<dim3(G4H / 128, (T_ * B_) / 128), 256>>>(src, emb_src, Wl, bl);
    k_lstm_mma<<<NCTA, NTHR, SM_TOT>>>(Wl, tgt);
    k_proj_softmax<<<(T_ * B_) / 32, 256>>>(Wp, bp, out);
}